// round 6
// baseline (speedup 1.0000x reference)
#include <cuda_runtime.h>
#include <math.h>
#include <stdint.h>

// ---------------- problem constants ----------------
#define NTOK   2048
#define NEXP   64
#define TOPK   6
#define CAP    512
#define HDIM   2048
#define IDIM   768
#define TWOI   1536
#define SIDIM  1536

// ---------------- tile config ----------------
#define BK   16
#define NTH  256             // 8 warps
#define LD1  136             // smem stride (words) for 128-wide tiles; 136 % 32 == 8
#define LD2  264             // smem stride for 256-wide tiles;        264 % 32 == 8
#define SWZ1(k, i) ((k) * LD1 + ((i) ^ ((((k) >> 2) & 3) << 3)))
#define SWZ2(k, i) ((k) * LD2 + ((i) ^ ((((k) >> 2) & 3) << 3)))

#define ATILE  (BK * LD1)    // 2176 words
#define BTILE2 (BK * LD2)    // 4224 words
#define SWIGLU_SMEM (6 * ATILE * 4)              // 2 stages x (A,Bg,Bu) = 52224 B
#define GEMM_SMEM   (2 * (ATILE + BTILE2) * 4)   // 2 stages x (A,B256)  = 51200 B

// ---------------- scratch ----------------
__device__ int   g_counts[NEXP];
__device__ int   g_buf_tok[NEXP * CAP];
__device__ float g_buf_w[NEXP * CAP];
__device__ float g_logits[NTOK * NEXP];
__device__ float g_hid[(size_t)NEXP * CAP * IDIM];   // ~100 MB
__device__ float g_shid[(size_t)NTOK * SIDIM];       // ~12.6 MB

// ---------------- helpers ----------------
__device__ __forceinline__ unsigned f2tf(float x) {
    unsigned y;
    asm("cvt.rna.tf32.f32 %0, %1;" : "=r"(y) : "f"(x));
    return y;
}
__device__ __forceinline__ float tfs(float x) { return __uint_as_float(f2tf(x)); }
__device__ __forceinline__ void mma8(float c[4], const unsigned a[4], const unsigned b[2]) {
    asm volatile(
        "mma.sync.aligned.m16n8k8.row.col.f32.tf32.tf32.f32 "
        "{%0,%1,%2,%3}, {%4,%5,%6,%7}, {%8,%9}, {%0,%1,%2,%3};"
        : "+f"(c[0]), "+f"(c[1]), "+f"(c[2]), "+f"(c[3])
        : "r"(a[0]), "r"(a[1]), "r"(a[2]), "r"(a[3]), "r"(b[0]), "r"(b[1]));
}
__device__ __forceinline__ float silu_f(float v) { return v / (1.0f + expf(-v)); }

// ================= fused SwiGLU up-projection =================
// hid = silu(A @ op(Bg)) * (A @ op(Bu)), block tile 128(M) x 128(N), warp 64x32 dual-acc.
// BNK=1: Bg/Bu are [N,K] row-major.  BNK=0: Bg/Bu are [K,N] (row stride ldb).
// EXPERT: blockIdx.z = expert; GATHER: A rows gathered via g_buf_tok.
template<int BNK, int EXPERT, int GATHER>
__global__ __launch_bounds__(NTH) void k_swiglu(
    const float* __restrict__ Abase, const float* __restrict__ Bg0,
    const float* __restrict__ Bu0, float* __restrict__ C,
    int Kd, int ldb, int ldc, long sB, long sC)
{
    extern __shared__ float sm[];
    __shared__ int s_tok[128];

    const int tid = threadIdx.x;
    const int warp = tid >> 5, lane = tid & 31;
    const int wm = warp >> 2, wn = warp & 3;     // 2(M) x 4(N)
    const int gq = lane >> 2, tq = lane & 3;
    const int m0 = blockIdx.y * 128, n0 = blockIdx.x * 128;

    int e = 0, cnt = 0x40000000;
    if (EXPERT) {
        e = blockIdx.z;
        cnt = g_counts[e];
        if (m0 >= cnt) return;
    }
    if (GATHER) {
        if (tid < 128) {
            int p = m0 + tid;
            s_tok[tid] = (p < cnt) ? g_buf_tok[e * CAP + p] : 0;
        }
        __syncthreads();
    }

    // smem stage bases (words): A | Bg | Bu, two stages each
    float* As = sm;
    float* Bgs = sm + 2 * ATILE;
    float* Bus = sm + 4 * ATILE;

    // ---- loader indices ----
    const int asel = tid & 3;           // k-quad
    const int axor = asel << 3;
    const int a_r0 = tid >> 2;          // 0..63 (rows r0, r0+64)

    const float* pa[2];
#pragma unroll
    for (int j = 0; j < 2; j++) {
        int r = a_r0 + j * 64;
        if (GATHER) pa[j] = Abase + (size_t)s_tok[r] * Kd + asel * 4;
        else        pa[j] = Abase + (size_t)(m0 + r) * Kd + asel * 4;
    }
    const float* pbg[2];
    const float* pbu[2];
    const int b_kr = tid >> 5;          // BNK=0: k rows kr, kr+8
    const int b_nc = (tid & 31) * 4;
#pragma unroll
    for (int j = 0; j < 2; j++) {
        if (BNK) {
            int r = a_r0 + j * 64;
            pbg[j] = Bg0 + (EXPERT ? (size_t)e * sB : 0) + (size_t)(n0 + r) * Kd + asel * 4;
            pbu[j] = Bu0 + (EXPERT ? (size_t)e * sB : 0) + (size_t)(n0 + r) * Kd + asel * 4;
        } else {
            int kr = b_kr + j * 8;
            pbg[j] = Bg0 + (EXPERT ? (size_t)e * sB : 0) + (size_t)kr * ldb + n0 + b_nc;
            pbu[j] = Bu0 + (EXPERT ? (size_t)e * sB : 0) + (size_t)kr * ldb + n0 + b_nc;
        }
    }
    const long bumpB = BNK ? (long)BK : (long)BK * ldb;

    float4 ra[2], rg[2], ru[2];
    auto LDG = [&]() {
#pragma unroll
        for (int j = 0; j < 2; j++) { ra[j] = *(const float4*)pa[j];  pa[j] += BK; }
#pragma unroll
        for (int j = 0; j < 2; j++) { rg[j] = *(const float4*)pbg[j]; pbg[j] += bumpB; }
#pragma unroll
        for (int j = 0; j < 2; j++) { ru[j] = *(const float4*)pbu[j]; pbu[j] += bumpB; }
    };
    auto STS = [&](int buf) {
        float* A = As + buf * ATILE;
        float* G = Bgs + buf * ATILE;
        float* U = Bus + buf * ATILE;
#pragma unroll
        for (int j = 0; j < 2; j++) {
            int r = a_r0 + j * 64;
            float* d = &A[asel * 4 * LD1 + (r ^ axor)];
            d[0] = tfs(ra[j].x); d[LD1] = tfs(ra[j].y);
            d[2 * LD1] = tfs(ra[j].z); d[3 * LD1] = tfs(ra[j].w);
        }
        if (BNK) {
#pragma unroll
            for (int j = 0; j < 2; j++) {
                int r = a_r0 + j * 64;
                float* d = &G[asel * 4 * LD1 + (r ^ axor)];
                d[0] = tfs(rg[j].x); d[LD1] = tfs(rg[j].y);
                d[2 * LD1] = tfs(rg[j].z); d[3 * LD1] = tfs(rg[j].w);
                float* d2 = &U[asel * 4 * LD1 + (r ^ axor)];
                d2[0] = tfs(ru[j].x); d2[LD1] = tfs(ru[j].y);
                d2[2 * LD1] = tfs(ru[j].z); d2[3 * LD1] = tfs(ru[j].w);
            }
        } else {
#pragma unroll
            for (int j = 0; j < 2; j++) {
                int kr = b_kr + j * 8;
                int off = kr * LD1 + (b_nc ^ (((kr >> 2) & 3) << 3));
                *(float4*)&G[off] = make_float4(tfs(rg[j].x), tfs(rg[j].y), tfs(rg[j].z), tfs(rg[j].w));
                *(float4*)&U[off] = make_float4(tfs(ru[j].x), tfs(ru[j].y), tfs(ru[j].z), tfs(ru[j].w));
            }
        }
    };

    float accg[4][4][4], accu[4][4][4];
#pragma unroll
    for (int mt = 0; mt < 4; mt++)
#pragma unroll
        for (int nt = 0; nt < 4; nt++)
#pragma unroll
            for (int r = 0; r < 4; r++) { accg[mt][nt][r] = 0.0f; accu[mt][nt][r] = 0.0f; }

    const int nslab = Kd / BK;
    LDG();
    STS(0);
    __syncthreads();

    for (int s = 0; s < nslab; s++) {
        const int buf = s & 1;
        if (s + 1 < nslab) LDG();
        const float* A = As + buf * ATILE;
        const float* G = Bgs + buf * ATILE;
        const float* U = Bus + buf * ATILE;
#pragma unroll
        for (int kk = 0; kk < BK; kk += 8) {
            unsigned af[4][4], bg[4][2], bu[4][2];
#pragma unroll
            for (int mt = 0; mt < 4; mt++) {
                int rb0 = wm * 64 + mt * 16 + gq;
                af[mt][0] = __float_as_uint(A[SWZ1(kk + tq,     rb0)]);
                af[mt][1] = __float_as_uint(A[SWZ1(kk + tq,     rb0 + 8)]);
                af[mt][2] = __float_as_uint(A[SWZ1(kk + tq + 4, rb0)]);
                af[mt][3] = __float_as_uint(A[SWZ1(kk + tq + 4, rb0 + 8)]);
            }
#pragma unroll
            for (int nt = 0; nt < 4; nt++) {
                int cb = wn * 32 + nt * 8 + gq;
                bg[nt][0] = __float_as_uint(G[SWZ1(kk + tq,     cb)]);
                bg[nt][1] = __float_as_uint(G[SWZ1(kk + tq + 4, cb)]);
                bu[nt][0] = __float_as_uint(U[SWZ1(kk + tq,     cb)]);
                bu[nt][1] = __float_as_uint(U[SWZ1(kk + tq + 4, cb)]);
            }
#pragma unroll
            for (int mt = 0; mt < 4; mt++)
#pragma unroll
                for (int nt = 0; nt < 4; nt++) {
                    mma8(accg[mt][nt], af[mt], bg[nt]);
                    mma8(accu[mt][nt], af[mt], bu[nt]);
                }
        }
        if (s + 1 < nslab) {
            __syncthreads();
            STS((s + 1) & 1);
            __syncthreads();
        }
    }

    // ---- epilogue: silu(g)*u ----
#pragma unroll
    for (int mt = 0; mt < 4; mt++)
#pragma unroll
        for (int nt = 0; nt < 4; nt++)
#pragma unroll
            for (int r = 0; r < 4; r++) {
                int row = wm * 64 + mt * 16 + gq + ((r & 2) ? 8 : 0);
                int col = wn * 32 + nt * 8 + tq * 2 + (r & 1);
                int gm = m0 + row;
                if (EXPERT && gm >= cnt) continue;
                float g = accg[mt][nt][r], u = accu[mt][nt][r];
                float* dst = C + (EXPERT ? (size_t)e * sC : 0);
                dst[(size_t)gm * ldc + n0 + col] = silu_f(g) * u;
            }
}

// ================= down-projection GEMM (128x256 block, 64x64 warp) =================
// C[M,N] = A[M,K] @ op(B).  BNK=1: B [N,K].  BNK=0: B [K,N] (ldb).
// EXPERT/ATOMIC as before.
template<int BNK, int EXPERT, int ATOMIC>
__global__ __launch_bounds__(NTH) void k_gemm(
    const float* __restrict__ Abase, const float* __restrict__ Bbase,
    float* __restrict__ C, int Kd, int ldb, int ldc,
    long sA, long sB)
{
    extern __shared__ float sm[];
    __shared__ int   s_tok[128];
    __shared__ float s_w[128];

    const int tid = threadIdx.x;
    const int warp = tid >> 5, lane = tid & 31;
    const int wm = warp >> 2, wn = warp & 3;     // 2(M) x 4(N), warp tile 64x64
    const int gq = lane >> 2, tq = lane & 3;
    const int m0 = blockIdx.y * 128, n0 = blockIdx.x * 256;

    int e = 0, cnt = 0x40000000;
    if (EXPERT) {
        e = blockIdx.z;
        cnt = g_counts[e];
        if (m0 >= cnt) return;
    }
    if (ATOMIC) {
        if (tid < 128) {
            int p = m0 + tid;
            int ok = (p < cnt);
            s_tok[tid] = ok ? g_buf_tok[e * CAP + p] : 0;
            s_w[tid]   = ok ? g_buf_w[e * CAP + p] : 0.0f;
        }
        __syncthreads();
    }

    float* As = sm;                       // 2 x ATILE
    float* Bs = sm + 2 * ATILE;           // 2 x BTILE2

    const int asel = tid & 3;
    const int axor = asel << 3;
    const int a_r0 = tid >> 2;            // 0..63

    const float* pa[2];
#pragma unroll
    for (int j = 0; j < 2; j++) {
        int r = a_r0 + j * 64;
        pa[j] = Abase + (EXPERT ? (size_t)e * sA : 0) + (size_t)(m0 + r) * Kd + asel * 4;
    }
    const float* pb[4];
    const int b_kr = tid >> 6;            // BNK=0: 0..3 (+4j)
    const int b_nc = (tid & 63) * 4;
#pragma unroll
    for (int j = 0; j < 4; j++) {
        if (BNK) {
            int r = a_r0 + j * 64;        // 0..255
            pb[j] = Bbase + (EXPERT ? (size_t)e * sB : 0) + (size_t)(n0 + r) * Kd + asel * 4;
        } else {
            int kr = b_kr + j * 4;
            pb[j] = Bbase + (EXPERT ? (size_t)e * sB : 0) + (size_t)kr * ldb + n0 + b_nc;
        }
    }
    const long bumpB = BNK ? (long)BK : (long)BK * ldb;

    float4 ra[2], rb[4];
    auto LDG = [&]() {
#pragma unroll
        for (int j = 0; j < 2; j++) { ra[j] = *(const float4*)pa[j]; pa[j] += BK; }
#pragma unroll
        for (int j = 0; j < 4; j++) { rb[j] = *(const float4*)pb[j]; pb[j] += bumpB; }
    };
    auto STS = [&](int buf) {
        float* A = As + buf * ATILE;
        float* B = Bs + buf * BTILE2;
#pragma unroll
        for (int j = 0; j < 2; j++) {
            int r = a_r0 + j * 64;
            float* d = &A[asel * 4 * LD1 + (r ^ axor)];
            d[0] = tfs(ra[j].x); d[LD1] = tfs(ra[j].y);
            d[2 * LD1] = tfs(ra[j].z); d[3 * LD1] = tfs(ra[j].w);
        }
        if (BNK) {
#pragma unroll
            for (int j = 0; j < 4; j++) {
                int r = a_r0 + j * 64;
                float* d = &B[asel * 4 * LD2 + (r ^ axor)];
                d[0] = tfs(rb[j].x); d[LD2] = tfs(rb[j].y);
                d[2 * LD2] = tfs(rb[j].z); d[3 * LD2] = tfs(rb[j].w);
            }
        } else {
#pragma unroll
            for (int j = 0; j < 4; j++) {
                int kr = b_kr + j * 4;
                int off = kr * LD2 + (b_nc ^ (((kr >> 2) & 3) << 3));
                *(float4*)&B[off] = make_float4(tfs(rb[j].x), tfs(rb[j].y), tfs(rb[j].z), tfs(rb[j].w));
            }
        }
    };

    float acc[4][8][4];
#pragma unroll
    for (int mt = 0; mt < 4; mt++)
#pragma unroll
        for (int nt = 0; nt < 8; nt++)
#pragma unroll
            for (int r = 0; r < 4; r++) acc[mt][nt][r] = 0.0f;

    const int nslab = Kd / BK;
    LDG();
    STS(0);
    __syncthreads();

    for (int s = 0; s < nslab; s++) {
        const int buf = s & 1;
        if (s + 1 < nslab) LDG();
        const float* A = As + buf * ATILE;
        const float* B = Bs + buf * BTILE2;
#pragma unroll
        for (int kk = 0; kk < BK; kk += 8) {
            unsigned af[4][4], bf[8][2];
#pragma unroll
            for (int mt = 0; mt < 4; mt++) {
                int rb0 = wm * 64 + mt * 16 + gq;
                af[mt][0] = __float_as_uint(A[SWZ1(kk + tq,     rb0)]);
                af[mt][1] = __float_as_uint(A[SWZ1(kk + tq,     rb0 + 8)]);
                af[mt][2] = __float_as_uint(A[SWZ1(kk + tq + 4, rb0)]);
                af[mt][3] = __float_as_uint(A[SWZ1(kk + tq + 4, rb0 + 8)]);
            }
#pragma unroll
            for (int nt = 0; nt < 8; nt++) {
                int cb = wn * 64 + nt * 8 + gq;
                bf[nt][0] = __float_as_uint(B[SWZ2(kk + tq,     cb)]);
                bf[nt][1] = __float_as_uint(B[SWZ2(kk + tq + 4, cb)]);
            }
#pragma unroll
            for (int mt = 0; mt < 4; mt++)
#pragma unroll
                for (int nt = 0; nt < 8; nt++)
                    mma8(acc[mt][nt], af[mt], bf[nt]);
        }
        if (s + 1 < nslab) {
            __syncthreads();
            STS((s + 1) & 1);
            __syncthreads();
        }
    }

    // ---- epilogue ----
#pragma unroll
    for (int mt = 0; mt < 4; mt++)
#pragma unroll
        for (int nt = 0; nt < 8; nt++)
#pragma unroll
            for (int r = 0; r < 4; r++) {
                int row = wm * 64 + mt * 16 + gq + ((r & 2) ? 8 : 0);
                int col = wn * 64 + nt * 8 + tq * 2 + (r & 1);
                int gm = m0 + row;
                if (EXPERT && gm >= cnt) continue;
                if (ATOMIC) {
                    atomicAdd(&C[(size_t)s_tok[row] * ldc + n0 + col],
                              acc[mt][nt][r] * s_w[row]);
                } else {
                    C[(size_t)gm * ldc + n0 + col] = acc[mt][nt][r];
                }
            }
}

// ================= router logits: 3xTF32 (near-fp32) =================
#define RTH 128
__global__ __launch_bounds__(RTH) void k_router_gemm(const float* __restrict__ A,
                                                     const float* __restrict__ B,
                                                     float* __restrict__ C) {
    __shared__ float As[16][64 + 4];
    __shared__ float Bsm[16][64 + 4];
    int tid = threadIdx.x;
    int warp = tid >> 5, lane = tid & 31;
    int wm = warp >> 1, wn = warp & 1, gq = lane >> 2, tq = lane & 3;
    int m0 = blockIdx.y * 64;

    const float* Ab = A + (size_t)m0 * HDIM;
    const float* Bb = B;

    float acc[2][4][4];
#pragma unroll
    for (int mt = 0; mt < 2; mt++)
#pragma unroll
        for (int nt = 0; nt < 4; nt++)
#pragma unroll
            for (int r = 0; r < 4; r++) acc[mt][nt][r] = 0.0f;

    for (int k0 = 0; k0 < HDIM; k0 += 16) {
        __syncthreads();
#pragma unroll
        for (int j = 0; j < 2; j++) {
            int it = tid + j * RTH;
            int r = it >> 2, c4 = it & 3;
            float4 va = *(const float4*)(Ab + (size_t)r * HDIM + k0 + c4 * 4);
            As[c4 * 4 + 0][r] = va.x; As[c4 * 4 + 1][r] = va.y;
            As[c4 * 4 + 2][r] = va.z; As[c4 * 4 + 3][r] = va.w;
            float4 vb = *(const float4*)(Bb + (size_t)r * HDIM + k0 + c4 * 4);
            Bsm[c4 * 4 + 0][r] = vb.x; Bsm[c4 * 4 + 1][r] = vb.y;
            Bsm[c4 * 4 + 2][r] = vb.z; Bsm[c4 * 4 + 3][r] = vb.w;
        }
        __syncthreads();
#pragma unroll
        for (int kk = 0; kk < 16; kk += 8) {
            float af[2][4], bfv[4][2];
#pragma unroll
            for (int mt = 0; mt < 2; mt++) {
                int rb = wm * 32 + mt * 16;
                af[mt][0] = As[kk + tq    ][rb + gq    ];
                af[mt][1] = As[kk + tq    ][rb + gq + 8];
                af[mt][2] = As[kk + tq + 4][rb + gq    ];
                af[mt][3] = As[kk + tq + 4][rb + gq + 8];
            }
#pragma unroll
            for (int nt = 0; nt < 4; nt++) {
                int cb = wn * 32 + nt * 8 + gq;
                bfv[nt][0] = Bsm[kk + tq    ][cb];
                bfv[nt][1] = Bsm[kk + tq + 4][cb];
            }
            unsigned ah[2][4], al[2][4], bh[4][2], bl[4][2];
#pragma unroll
            for (int mt = 0; mt < 2; mt++)
#pragma unroll
                for (int i = 0; i < 4; i++) {
                    ah[mt][i] = f2tf(af[mt][i]);
                    al[mt][i] = f2tf(af[mt][i] - __uint_as_float(ah[mt][i]));
                }
#pragma unroll
            for (int nt = 0; nt < 4; nt++)
#pragma unroll
                for (int i = 0; i < 2; i++) {
                    bh[nt][i] = f2tf(bfv[nt][i]);
                    bl[nt][i] = f2tf(bfv[nt][i] - __uint_as_float(bh[nt][i]));
                }
#pragma unroll
            for (int mt = 0; mt < 2; mt++)
#pragma unroll
                for (int nt = 0; nt < 4; nt++) {
                    mma8(acc[mt][nt], al[mt], bh[nt]);
                    mma8(acc[mt][nt], ah[mt], bl[nt]);
                    mma8(acc[mt][nt], ah[mt], bh[nt]);
                }
        }
    }
#pragma unroll
    for (int mt = 0; mt < 2; mt++)
#pragma unroll
        for (int nt = 0; nt < 4; nt++)
#pragma unroll
            for (int r = 0; r < 4; r++) {
                int row = wm * 32 + mt * 16 + gq + ((r & 2) ? 8 : 0);
                int col = wn * 32 + nt * 8 + tq * 2 + (r & 1);
                C[(size_t)(m0 + row) * NEXP + col] = acc[mt][nt][r];
            }
}

// ================= router softmax + top-6 + dispatch =================
__global__ void k_init() {
    if (threadIdx.x < NEXP) g_counts[threadIdx.x] = 0;
}

__global__ void k_router() {
    int warp = threadIdx.x >> 5, lane = threadIdx.x & 31;
    int t = blockIdx.x * 8 + warp;
    float v0 = g_logits[t * NEXP + lane];
    float v1 = g_logits[t * NEXP + 32 + lane];
    float m = fmaxf(v0, v1);
#pragma unroll
    for (int s = 16; s > 0; s >>= 1) m = fmaxf(m, __shfl_xor_sync(0xffffffffu, m, s));
    float e0 = expf(v0 - m), e1 = expf(v1 - m);
    float sum = e0 + e1;
#pragma unroll
    for (int s = 16; s > 0; s >>= 1) sum += __shfl_xor_sync(0xffffffffu, sum, s);
    float inv = 1.0f / sum;
    float p0 = e0 * inv, p1 = e1 * inv;

#pragma unroll
    for (int k = 0; k < TOPK; k++) {
        float bv; int bi;
        if (p0 >= p1) { bv = p0; bi = lane; } else { bv = p1; bi = lane + 32; }
#pragma unroll
        for (int s = 16; s > 0; s >>= 1) {
            float ov = __shfl_xor_sync(0xffffffffu, bv, s);
            int   oi = __shfl_xor_sync(0xffffffffu, bi, s);
            if (ov > bv || (ov == bv && oi < bi)) { bv = ov; bi = oi; }
        }
        if (lane == 0) {
            int pos = atomicAdd(&g_counts[bi], 1);
            if (pos < CAP) {
                g_buf_tok[bi * CAP + pos] = t;
                g_buf_w[bi * CAP + pos] = bv;
            }
        }
        if (bi < 32) { if (lane == bi) p0 = -1.0f; }
        else         { if (lane == bi - 32) p1 = -1.0f; }
    }
}

// ================= launch =================
extern "C" void kernel_launch(void* const* d_in, const int* in_sizes, int n_in,
                              void* d_out, int out_size) {
    const float* x   = (const float*)d_in[0];
    const float* gw  = (const float*)d_in[1];
    const float* gup = (const float*)d_in[2];
    const float* dwn = (const float*)d_in[3];
    const float* sgw = (const float*)d_in[4];
    const float* suw = (const float*)d_in[5];
    const float* sdw = (const float*)d_in[6];
    float* out = (float*)d_out;

    float *p_logits, *p_hid, *p_shid;
    cudaGetSymbolAddress((void**)&p_logits, g_logits);
    cudaGetSymbolAddress((void**)&p_hid,  g_hid);
    cudaGetSymbolAddress((void**)&p_shid, g_shid);

    cudaFuncSetAttribute(k_swiglu<1,0,0>, cudaFuncAttributeMaxDynamicSharedMemorySize, SWIGLU_SMEM);
    cudaFuncSetAttribute(k_swiglu<0,1,1>, cudaFuncAttributeMaxDynamicSharedMemorySize, SWIGLU_SMEM);
    cudaFuncSetAttribute(k_gemm<1,0,0>,   cudaFuncAttributeMaxDynamicSharedMemorySize, GEMM_SMEM);
    cudaFuncSetAttribute(k_gemm<0,1,1>,   cudaFuncAttributeMaxDynamicSharedMemorySize, GEMM_SMEM);

    k_init<<<1, 64>>>();
    // router: near-fp32 logits so top-k matches reference exactly
    k_router_gemm<<<dim3(1, NTOK / 64), RTH>>>(x, gw, p_logits);
    k_router<<<NTOK / 8, 256>>>();

    // shared experts: fused SwiGLU up ([N,K] weights), then down -> out (plain store covers out)
    k_swiglu<1,0,0><<<dim3(SIDIM / 128, NTOK / 128), NTH, SWIGLU_SMEM>>>(
        x, sgw, suw, p_shid, HDIM, 0, SIDIM, 0, 0);
    k_gemm<1,0,0><<<dim3(HDIM / 256, NTOK / 128), NTH, GEMM_SMEM>>>(
        p_shid, sdw, out, SIDIM, 0, HDIM, 0, 0);

    // routed experts: fused SwiGLU gate_up (gathered A, [K,N] weights), down (atomic scatter-add)
    k_swiglu<0,1,1><<<dim3(IDIM / 128, CAP / 128, NEXP), NTH, SWIGLU_SMEM>>>(
        x, gup, gup + IDIM, p_hid, HDIM, TWOI, IDIM, (long)HDIM * TWOI, (long)CAP * IDIM);
    k_gemm<0,1,1><<<dim3(HDIM / 256, CAP / 128, NEXP), NTH, GEMM_SMEM>>>(
        p_hid, dwn, out, IDIM, HDIM, HDIM, (long)CAP * IDIM, (long)IDIM * HDIM);
}

// round 7
// speedup vs baseline: 1.0003x; 1.0003x over previous
#include <cuda_runtime.h>
#include <math.h>
#include <stdint.h>

// ---------------- problem constants ----------------
#define NTOK   2048
#define NEXP   64
#define TOPK   6
#define CAP    512
#define HDIM   2048
#define IDIM   768
#define TWOI   1536
#define SIDIM  1536

// ---------------- tile config ----------------
#define BK   16
#define NTH  256             // 8 warps
#define LD1  136             // smem stride (words) for 128-wide tiles; 136 % 32 == 8
#define LD2  264             // smem stride for 256-wide tiles;        264 % 32 == 8
#define SWZ1(k, i) ((k) * LD1 + ((i) ^ ((((k) >> 2) & 3) << 3)))
#define SWZ2(k, i) ((k) * LD2 + ((i) ^ ((((k) >> 2) & 3) << 3)))

#define ATILE  (BK * LD1)    // 2176 words
#define BTILE2 (BK * LD2)    // 4224 words
#define SWIGLU_SMEM (9 * ATILE * 4)                  // 3 stages x (A,Bg,Bu) = 78336 B
#define GEMM_SMEM   (3 * (ATILE + BTILE2) * 4)       // 3 stages x (A,B256)  = 76800 B

// ---------------- scratch ----------------
__device__ int   g_counts[NEXP];
__device__ int   g_buf_tok[NEXP * CAP];
__device__ float g_buf_w[NEXP * CAP];
__device__ float g_logits[NTOK * NEXP];
__device__ float g_hid[(size_t)NEXP * CAP * IDIM];   // ~100 MB
__device__ float g_shid[(size_t)NTOK * SIDIM];       // ~12.6 MB

// ---------------- helpers ----------------
__device__ __forceinline__ unsigned f2tf(float x) {
    unsigned y;
    asm("cvt.rna.tf32.f32 %0, %1;" : "=r"(y) : "f"(x));
    return y;
}
__device__ __forceinline__ float tfs(float x) { return __uint_as_float(f2tf(x)); }
__device__ __forceinline__ void mma8(float c[4], const unsigned a[4], const unsigned b[2]) {
    asm volatile(
        "mma.sync.aligned.m16n8k8.row.col.f32.tf32.tf32.f32 "
        "{%0,%1,%2,%3}, {%4,%5,%6,%7}, {%8,%9}, {%0,%1,%2,%3};"
        : "+f"(c[0]), "+f"(c[1]), "+f"(c[2]), "+f"(c[3])
        : "r"(a[0]), "r"(a[1]), "r"(a[2]), "r"(a[3]), "r"(b[0]), "r"(b[1]));
}
__device__ __forceinline__ float silu_f(float v) { return v / (1.0f + expf(-v)); }

// ================= fused SwiGLU up-projection =================
// hid = silu(A @ op(Bg)) * (A @ op(Bu)), block 128(M) x 128(N), warp 64x32 dual-acc.
// BNK=1: Bg/Bu are [N,K] row-major.  BNK=0: Bg/Bu are [K,N] (row stride ldb).
template<int BNK, int EXPERT, int GATHER>
__global__ __launch_bounds__(NTH) void k_swiglu(
    const float* __restrict__ Abase, const float* __restrict__ Bg0,
    const float* __restrict__ Bu0, float* __restrict__ C,
    int Kd, int ldb, int ldc, long sB, long sC)
{
    extern __shared__ float sm[];
    __shared__ int s_tok[128];

    const int tid = threadIdx.x;
    const int warp = tid >> 5, lane = tid & 31;
    const int wm = warp >> 2, wn = warp & 3;     // 2(M) x 4(N)
    const int gq = lane >> 2, tq = lane & 3;
    const int m0 = blockIdx.y * 128, n0 = blockIdx.x * 128;

    int e = 0, cnt = 0x40000000;
    if (EXPERT) {
        e = blockIdx.z;
        cnt = g_counts[e];
        if (m0 >= cnt) return;
    }
    if (GATHER) {
        if (tid < 128) {
            int p = m0 + tid;
            s_tok[tid] = (p < cnt) ? g_buf_tok[e * CAP + p] : 0;
        }
        __syncthreads();
    }

    float* As  = sm;                 // 3 x ATILE
    float* Bgs = sm + 3 * ATILE;     // 3 x ATILE
    float* Bus = sm + 6 * ATILE;     // 3 x ATILE

    const int asel = tid & 3;
    const int axor = asel << 3;
    const int a_r0 = tid >> 2;       // 0..63 (rows r0, r0+64)

    const float* pa[2];
#pragma unroll
    for (int j = 0; j < 2; j++) {
        int r = a_r0 + j * 64;
        if (GATHER) pa[j] = Abase + (size_t)s_tok[r] * Kd + asel * 4;
        else        pa[j] = Abase + (size_t)(m0 + r) * Kd + asel * 4;
    }
    const float* pbg[2];
    const float* pbu[2];
    const int b_kr = tid >> 5;
    const int b_nc = (tid & 31) * 4;
#pragma unroll
    for (int j = 0; j < 2; j++) {
        if (BNK) {
            int r = a_r0 + j * 64;
            pbg[j] = Bg0 + (EXPERT ? (size_t)e * sB : 0) + (size_t)(n0 + r) * Kd + asel * 4;
            pbu[j] = Bu0 + (EXPERT ? (size_t)e * sB : 0) + (size_t)(n0 + r) * Kd + asel * 4;
        } else {
            int kr = b_kr + j * 8;
            pbg[j] = Bg0 + (EXPERT ? (size_t)e * sB : 0) + (size_t)kr * ldb + n0 + b_nc;
            pbu[j] = Bu0 + (EXPERT ? (size_t)e * sB : 0) + (size_t)kr * ldb + n0 + b_nc;
        }
    }
    const long bumpB = BNK ? (long)BK : (long)BK * ldb;

    float4 ra[2], rg[2], ru[2];
    auto LDG = [&]() {
#pragma unroll
        for (int j = 0; j < 2; j++) { ra[j] = *(const float4*)pa[j];  pa[j] += BK; }
#pragma unroll
        for (int j = 0; j < 2; j++) { rg[j] = *(const float4*)pbg[j]; pbg[j] += bumpB; }
#pragma unroll
        for (int j = 0; j < 2; j++) { ru[j] = *(const float4*)pbu[j]; pbu[j] += bumpB; }
    };
    auto STS = [&](int buf) {
        float* A = As + buf * ATILE;
        float* G = Bgs + buf * ATILE;
        float* U = Bus + buf * ATILE;
#pragma unroll
        for (int j = 0; j < 2; j++) {
            int r = a_r0 + j * 64;
            float* d = &A[asel * 4 * LD1 + (r ^ axor)];
            d[0] = tfs(ra[j].x); d[LD1] = tfs(ra[j].y);
            d[2 * LD1] = tfs(ra[j].z); d[3 * LD1] = tfs(ra[j].w);
        }
        if (BNK) {
#pragma unroll
            for (int j = 0; j < 2; j++) {
                int r = a_r0 + j * 64;
                float* d = &G[asel * 4 * LD1 + (r ^ axor)];
                d[0] = tfs(rg[j].x); d[LD1] = tfs(rg[j].y);
                d[2 * LD1] = tfs(rg[j].z); d[3 * LD1] = tfs(rg[j].w);
                float* d2 = &U[asel * 4 * LD1 + (r ^ axor)];
                d2[0] = tfs(ru[j].x); d2[LD1] = tfs(ru[j].y);
                d2[2 * LD1] = tfs(ru[j].z); d2[3 * LD1] = tfs(ru[j].w);
            }
        } else {
#pragma unroll
            for (int j = 0; j < 2; j++) {
                int kr = b_kr + j * 8;
                int off = kr * LD1 + (b_nc ^ (((kr >> 2) & 3) << 3));
                *(float4*)&G[off] = make_float4(tfs(rg[j].x), tfs(rg[j].y), tfs(rg[j].z), tfs(rg[j].w));
                *(float4*)&U[off] = make_float4(tfs(ru[j].x), tfs(ru[j].y), tfs(ru[j].z), tfs(ru[j].w));
            }
        }
    };

    float accg[4][4][4], accu[4][4][4];
#pragma unroll
    for (int mt = 0; mt < 4; mt++)
#pragma unroll
        for (int nt = 0; nt < 4; nt++)
#pragma unroll
            for (int r = 0; r < 4; r++) { accg[mt][nt][r] = 0.0f; accu[mt][nt][r] = 0.0f; }

    const int nslab = Kd / BK;
    // ---- 3-stage pipeline prologue ----
    LDG(); STS(0);
    LDG(); STS(1);
    __syncthreads();

    int bc = 0, bs = 2;
    for (int s = 0; s < nslab; s++) {
        const bool pf = (s + 2 < nslab);
        if (pf) LDG();                        // fetch slab s+2 into staging regs
        const float* A = As + bc * ATILE;
        const float* G = Bgs + bc * ATILE;
        const float* U = Bus + bc * ATILE;
#pragma unroll
        for (int kk = 0; kk < BK; kk += 8) {
            unsigned af[4][4], bg[4][2], bu[4][2];
#pragma unroll
            for (int mt = 0; mt < 4; mt++) {
                int rb0 = wm * 64 + mt * 16 + gq;
                af[mt][0] = __float_as_uint(A[SWZ1(kk + tq,     rb0)]);
                af[mt][1] = __float_as_uint(A[SWZ1(kk + tq,     rb0 + 8)]);
                af[mt][2] = __float_as_uint(A[SWZ1(kk + tq + 4, rb0)]);
                af[mt][3] = __float_as_uint(A[SWZ1(kk + tq + 4, rb0 + 8)]);
            }
#pragma unroll
            for (int nt = 0; nt < 4; nt++) {
                int cb = wn * 32 + nt * 8 + gq;
                bg[nt][0] = __float_as_uint(G[SWZ1(kk + tq,     cb)]);
                bg[nt][1] = __float_as_uint(G[SWZ1(kk + tq + 4, cb)]);
                bu[nt][0] = __float_as_uint(U[SWZ1(kk + tq,     cb)]);
                bu[nt][1] = __float_as_uint(U[SWZ1(kk + tq + 4, cb)]);
            }
#pragma unroll
            for (int mt = 0; mt < 4; mt++)
#pragma unroll
                for (int nt = 0; nt < 4; nt++) {
                    mma8(accg[mt][nt], af[mt], bg[nt]);
                    mma8(accu[mt][nt], af[mt], bu[nt]);
                }
        }
        __syncthreads();
        if (pf) STS(bs);                      // overlaps with next slab's compute
        bc = (bc == 2) ? 0 : bc + 1;
        bs = (bs == 2) ? 0 : bs + 1;
    }

    // ---- epilogue: silu(g)*u ----
#pragma unroll
    for (int mt = 0; mt < 4; mt++)
#pragma unroll
        for (int nt = 0; nt < 4; nt++)
#pragma unroll
            for (int r = 0; r < 4; r++) {
                int row = wm * 64 + mt * 16 + gq + ((r & 2) ? 8 : 0);
                int col = wn * 32 + nt * 8 + tq * 2 + (r & 1);
                int gm = m0 + row;
                if (EXPERT && gm >= cnt) continue;
                float g = accg[mt][nt][r], u = accu[mt][nt][r];
                float* dst = C + (EXPERT ? (size_t)e * sC : 0);
                dst[(size_t)gm * ldc + n0 + col] = silu_f(g) * u;
            }
}

// ================= down-projection GEMM (128x256 block, 64x64 warp) =================
template<int BNK, int EXPERT, int ATOMIC>
__global__ __launch_bounds__(NTH) void k_gemm(
    const float* __restrict__ Abase, const float* __restrict__ Bbase,
    float* __restrict__ C, int Kd, int ldb, int ldc,
    long sA, long sB)
{
    extern __shared__ float sm[];
    __shared__ int   s_tok[128];
    __shared__ float s_w[128];

    const int tid = threadIdx.x;
    const int warp = tid >> 5, lane = tid & 31;
    const int wm = warp >> 2, wn = warp & 3;     // 2(M) x 4(N), warp tile 64x64
    const int gq = lane >> 2, tq = lane & 3;
    const int m0 = blockIdx.y * 128, n0 = blockIdx.x * 256;

    int e = 0, cnt = 0x40000000;
    if (EXPERT) {
        e = blockIdx.z;
        cnt = g_counts[e];
        if (m0 >= cnt) return;
    }
    if (ATOMIC) {
        if (tid < 128) {
            int p = m0 + tid;
            int ok = (p < cnt);
            s_tok[tid] = ok ? g_buf_tok[e * CAP + p] : 0;
            s_w[tid]   = ok ? g_buf_w[e * CAP + p] : 0.0f;
        }
        __syncthreads();
    }

    float* As = sm;                       // 3 x ATILE
    float* Bs = sm + 3 * ATILE;           // 3 x BTILE2

    const int asel = tid & 3;
    const int axor = asel << 3;
    const int a_r0 = tid >> 2;            // 0..63

    const float* pa[2];
#pragma unroll
    for (int j = 0; j < 2; j++) {
        int r = a_r0 + j * 64;
        pa[j] = Abase + (EXPERT ? (size_t)e * sA : 0) + (size_t)(m0 + r) * Kd + asel * 4;
    }
    const float* pb[4];
    const int b_kr = tid >> 6;            // BNK=0: 0..3 (+4j)
    const int b_nc = (tid & 63) * 4;
#pragma unroll
    for (int j = 0; j < 4; j++) {
        if (BNK) {
            int r = a_r0 + j * 64;        // 0..255
            pb[j] = Bbase + (EXPERT ? (size_t)e * sB : 0) + (size_t)(n0 + r) * Kd + asel * 4;
        } else {
            int kr = b_kr + j * 4;
            pb[j] = Bbase + (EXPERT ? (size_t)e * sB : 0) + (size_t)kr * ldb + n0 + b_nc;
        }
    }
    const long bumpB = BNK ? (long)BK : (long)BK * ldb;

    float4 ra[2], rb[4];
    auto LDG = [&]() {
#pragma unroll
        for (int j = 0; j < 2; j++) { ra[j] = *(const float4*)pa[j]; pa[j] += BK; }
#pragma unroll
        for (int j = 0; j < 4; j++) { rb[j] = *(const float4*)pb[j]; pb[j] += bumpB; }
    };
    auto STS = [&](int buf) {
        float* A = As + buf * ATILE;
        float* B = Bs + buf * BTILE2;
#pragma unroll
        for (int j = 0; j < 2; j++) {
            int r = a_r0 + j * 64;
            float* d = &A[asel * 4 * LD1 + (r ^ axor)];
            d[0] = tfs(ra[j].x); d[LD1] = tfs(ra[j].y);
            d[2 * LD1] = tfs(ra[j].z); d[3 * LD1] = tfs(ra[j].w);
        }
        if (BNK) {
#pragma unroll
            for (int j = 0; j < 4; j++) {
                int r = a_r0 + j * 64;
                float* d = &B[asel * 4 * LD2 + (r ^ axor)];
                d[0] = tfs(rb[j].x); d[LD2] = tfs(rb[j].y);
                d[2 * LD2] = tfs(rb[j].z); d[3 * LD2] = tfs(rb[j].w);
            }
        } else {
#pragma unroll
            for (int j = 0; j < 4; j++) {
                int kr = b_kr + j * 4;
                int off = kr * LD2 + (b_nc ^ (((kr >> 2) & 3) << 3));
                *(float4*)&B[off] = make_float4(tfs(rb[j].x), tfs(rb[j].y), tfs(rb[j].z), tfs(rb[j].w));
            }
        }
    };

    float acc[4][8][4];
#pragma unroll
    for (int mt = 0; mt < 4; mt++)
#pragma unroll
        for (int nt = 0; nt < 8; nt++)
#pragma unroll
            for (int r = 0; r < 4; r++) acc[mt][nt][r] = 0.0f;

    const int nslab = Kd / BK;
    // ---- 3-stage pipeline prologue ----
    LDG(); STS(0);
    LDG(); STS(1);
    __syncthreads();

    int bc = 0, bs = 2;
    for (int s = 0; s < nslab; s++) {
        const bool pf = (s + 2 < nslab);
        if (pf) LDG();
        const float* A = As + bc * ATILE;
        const float* B = Bs + bc * BTILE2;
#pragma unroll
        for (int kk = 0; kk < BK; kk += 8) {
            unsigned af[4][4], bf[8][2];
#pragma unroll
            for (int mt = 0; mt < 4; mt++) {
                int rb0 = wm * 64 + mt * 16 + gq;
                af[mt][0] = __float_as_uint(A[SWZ1(kk + tq,     rb0)]);
                af[mt][1] = __float_as_uint(A[SWZ1(kk + tq,     rb0 + 8)]);
                af[mt][2] = __float_as_uint(A[SWZ1(kk + tq + 4, rb0)]);
                af[mt][3] = __float_as_uint(A[SWZ1(kk + tq + 4, rb0 + 8)]);
            }
#pragma unroll
            for (int nt = 0; nt < 8; nt++) {
                int cb = wn * 64 + nt * 8 + gq;
                bf[nt][0] = __float_as_uint(B[SWZ2(kk + tq,     cb)]);
                bf[nt][1] = __float_as_uint(B[SWZ2(kk + tq + 4, cb)]);
            }
#pragma unroll
            for (int mt = 0; mt < 4; mt++)
#pragma unroll
                for (int nt = 0; nt < 8; nt++)
                    mma8(acc[mt][nt], af[mt], bf[nt]);
        }
        __syncthreads();
        if (pf) STS(bs);
        bc = (bc == 2) ? 0 : bc + 1;
        bs = (bs == 2) ? 0 : bs + 1;
    }

    // ---- epilogue ----
#pragma unroll
    for (int mt = 0; mt < 4; mt++)
#pragma unroll
        for (int nt = 0; nt < 8; nt++)
#pragma unroll
            for (int r = 0; r < 4; r++) {
                int row = wm * 64 + mt * 16 + gq + ((r & 2) ? 8 : 0);
                int col = wn * 64 + nt * 8 + tq * 2 + (r & 1);
                int gm = m0 + row;
                if (EXPERT && gm >= cnt) continue;
                if (ATOMIC) {
                    atomicAdd(&C[(size_t)s_tok[row] * ldc + n0 + col],
                              acc[mt][nt][r] * s_w[row]);
                } else {
                    C[(size_t)gm * ldc + n0 + col] = acc[mt][nt][r];
                }
            }
}

// ================= router logits: 3xTF32 (near-fp32) =================
#define RTH 128
__global__ __launch_bounds__(RTH) void k_router_gemm(const float* __restrict__ A,
                                                     const float* __restrict__ B,
                                                     float* __restrict__ C) {
    __shared__ float As[16][64 + 4];
    __shared__ float Bsm[16][64 + 4];
    int tid = threadIdx.x;
    int warp = tid >> 5, lane = tid & 31;
    int wm = warp >> 1, wn = warp & 1, gq = lane >> 2, tq = lane & 3;
    int m0 = blockIdx.y * 64;

    const float* Ab = A + (size_t)m0 * HDIM;
    const float* Bb = B;

    float acc[2][4][4];
#pragma unroll
    for (int mt = 0; mt < 2; mt++)
#pragma unroll
        for (int nt = 0; nt < 4; nt++)
#pragma unroll
            for (int r = 0; r < 4; r++) acc[mt][nt][r] = 0.0f;

    for (int k0 = 0; k0 < HDIM; k0 += 16) {
        __syncthreads();
#pragma unroll
        for (int j = 0; j < 2; j++) {
            int it = tid + j * RTH;
            int r = it >> 2, c4 = it & 3;
            float4 va = *(const float4*)(Ab + (size_t)r * HDIM + k0 + c4 * 4);
            As[c4 * 4 + 0][r] = va.x; As[c4 * 4 + 1][r] = va.y;
            As[c4 * 4 + 2][r] = va.z; As[c4 * 4 + 3][r] = va.w;
            float4 vb = *(const float4*)(Bb + (size_t)r * HDIM + k0 + c4 * 4);
            Bsm[c4 * 4 + 0][r] = vb.x; Bsm[c4 * 4 + 1][r] = vb.y;
            Bsm[c4 * 4 + 2][r] = vb.z; Bsm[c4 * 4 + 3][r] = vb.w;
        }
        __syncthreads();
#pragma unroll
        for (int kk = 0; kk < 16; kk += 8) {
            float af[2][4], bfv[4][2];
#pragma unroll
            for (int mt = 0; mt < 2; mt++) {
                int rb = wm * 32 + mt * 16;
                af[mt][0] = As[kk + tq    ][rb + gq    ];
                af[mt][1] = As[kk + tq    ][rb + gq + 8];
                af[mt][2] = As[kk + tq + 4][rb + gq    ];
                af[mt][3] = As[kk + tq + 4][rb + gq + 8];
            }
#pragma unroll
            for (int nt = 0; nt < 4; nt++) {
                int cb = wn * 32 + nt * 8 + gq;
                bfv[nt][0] = Bsm[kk + tq    ][cb];
                bfv[nt][1] = Bsm[kk + tq + 4][cb];
            }
            unsigned ah[2][4], al[2][4], bh[4][2], bl[4][2];
#pragma unroll
            for (int mt = 0; mt < 2; mt++)
#pragma unroll
                for (int i = 0; i < 4; i++) {
                    ah[mt][i] = f2tf(af[mt][i]);
                    al[mt][i] = f2tf(af[mt][i] - __uint_as_float(ah[mt][i]));
                }
#pragma unroll
            for (int nt = 0; nt < 4; nt++)
#pragma unroll
                for (int i = 0; i < 2; i++) {
                    bh[nt][i] = f2tf(bfv[nt][i]);
                    bl[nt][i] = f2tf(bfv[nt][i] - __uint_as_float(bh[nt][i]));
                }
#pragma unroll
            for (int mt = 0; mt < 2; mt++)
#pragma unroll
                for (int nt = 0; nt < 4; nt++) {
                    mma8(acc[mt][nt], al[mt], bh[nt]);
                    mma8(acc[mt][nt], ah[mt], bl[nt]);
                    mma8(acc[mt][nt], ah[mt], bh[nt]);
                }
        }
    }
#pragma unroll
    for (int mt = 0; mt < 2; mt++)
#pragma unroll
        for (int nt = 0; nt < 4; nt++)
#pragma unroll
            for (int r = 0; r < 4; r++) {
                int row = wm * 32 + mt * 16 + gq + ((r & 2) ? 8 : 0);
                int col = wn * 32 + nt * 8 + tq * 2 + (r & 1);
                C[(size_t)(m0 + row) * NEXP + col] = acc[mt][nt][r];
            }
}

// ================= router softmax + top-6 + dispatch =================
__global__ void k_init() {
    if (threadIdx.x < NEXP) g_counts[threadIdx.x] = 0;
}

__global__ void k_router() {
    int warp = threadIdx.x >> 5, lane = threadIdx.x & 31;
    int t = blockIdx.x * 8 + warp;
    float v0 = g_logits[t * NEXP + lane];
    float v1 = g_logits[t * NEXP + 32 + lane];
    float m = fmaxf(v0, v1);
#pragma unroll
    for (int s = 16; s > 0; s >>= 1) m = fmaxf(m, __shfl_xor_sync(0xffffffffu, m, s));
    float e0 = expf(v0 - m), e1 = expf(v1 - m);
    float sum = e0 + e1;
#pragma unroll
    for (int s = 16; s > 0; s >>= 1) sum += __shfl_xor_sync(0xffffffffu, sum, s);
    float inv = 1.0f / sum;
    float p0 = e0 * inv, p1 = e1 * inv;

#pragma unroll
    for (int k = 0; k < TOPK; k++) {
        float bv; int bi;
        if (p0 >= p1) { bv = p0; bi = lane; } else { bv = p1; bi = lane + 32; }
#pragma unroll
        for (int s = 16; s > 0; s >>= 1) {
            float ov = __shfl_xor_sync(0xffffffffu, bv, s);
            int   oi = __shfl_xor_sync(0xffffffffu, bi, s);
            if (ov > bv || (ov == bv && oi < bi)) { bv = ov; bi = oi; }
        }
        if (lane == 0) {
            int pos = atomicAdd(&g_counts[bi], 1);
            if (pos < CAP) {
                g_buf_tok[bi * CAP + pos] = t;
                g_buf_w[bi * CAP + pos] = bv;
            }
        }
        if (bi < 32) { if (lane == bi) p0 = -1.0f; }
        else         { if (lane == bi - 32) p1 = -1.0f; }
    }
}

// ================= launch =================
extern "C" void kernel_launch(void* const* d_in, const int* in_sizes, int n_in,
                              void* d_out, int out_size) {
    const float* x   = (const float*)d_in[0];
    const float* gw  = (const float*)d_in[1];
    const float* gup = (const float*)d_in[2];
    const float* dwn = (const float*)d_in[3];
    const float* sgw = (const float*)d_in[4];
    const float* suw = (const float*)d_in[5];
    const float* sdw = (const float*)d_in[6];
    float* out = (float*)d_out;

    float *p_logits, *p_hid, *p_shid;
    cudaGetSymbolAddress((void**)&p_logits, g_logits);
    cudaGetSymbolAddress((void**)&p_hid,  g_hid);
    cudaGetSymbolAddress((void**)&p_shid, g_shid);

    cudaFuncSetAttribute(k_swiglu<1,0,0>, cudaFuncAttributeMaxDynamicSharedMemorySize, SWIGLU_SMEM);
    cudaFuncSetAttribute(k_swiglu<0,1,1>, cudaFuncAttributeMaxDynamicSharedMemorySize, SWIGLU_SMEM);
    cudaFuncSetAttribute(k_gemm<1,0,0>,   cudaFuncAttributeMaxDynamicSharedMemorySize, GEMM_SMEM);
    cudaFuncSetAttribute(k_gemm<0,1,1>,   cudaFuncAttributeMaxDynamicSharedMemorySize, GEMM_SMEM);

    k_init<<<1, 64>>>();
    // router: near-fp32 logits so top-k matches reference exactly
    k_router_gemm<<<dim3(1, NTOK / 64), RTH>>>(x, gw, p_logits);
    k_router<<<NTOK / 8, 256>>>();

    // shared experts: fused SwiGLU up ([N,K] weights), then down -> out (plain store covers out)
    k_swiglu<1,0,0><<<dim3(SIDIM / 128, NTOK / 128), NTH, SWIGLU_SMEM>>>(
        x, sgw, suw, p_shid, HDIM, 0, SIDIM, 0, 0);
    k_gemm<1,0,0><<<dim3(HDIM / 256, NTOK / 128), NTH, GEMM_SMEM>>>(
        p_shid, sdw, out, SIDIM, 0, HDIM, 0, 0);

    // routed experts: fused SwiGLU gate_up (gathered A, [K,N] weights), down (atomic scatter-add)
    k_swiglu<0,1,1><<<dim3(IDIM / 128, CAP / 128, NEXP), NTH, SWIGLU_SMEM>>>(
        x, gup, gup + IDIM, p_hid, HDIM, TWOI, IDIM, (long)HDIM * TWOI, (long)CAP * IDIM);
    k_gemm<0,1,1><<<dim3(HDIM / 256, CAP / 128, NEXP), NTH, GEMM_SMEM>>>(
        p_hid, dwn, out, IDIM, HDIM, HDIM, (long)CAP * IDIM, (long)IDIM * HDIM);
}

// round 8
// speedup vs baseline: 1.2708x; 1.2704x over previous
#include <cuda_runtime.h>
#include <cuda_fp16.h>
#include <math.h>
#include <stdint.h>

// ---------------- problem constants ----------------
#define NTOK   2048
#define NEXP   64
#define TOPK   6
#define CAP    512
#define HDIM   2048
#define IDIM   768
#define TWOI   1536
#define SIDIM  1536

// ---------------- tile config ----------------
#define BK   16              // k per slab (halfs)
#define NTH  256             // 8 warps
#define RSA  48              // [row][k] tile row stride BYTES (16 halfs + 8 pad)
#define RSB  272             // [k][n] tile row stride BYTES (128 halfs + 8 pad)
#define TSLOT 6144           // bytes per tile slot (A:128*48; B-kn:16*272=4352 fits)

// ---------------- scratch ----------------
__device__ int   g_counts[NEXP];
__device__ int   g_buf_tok[NEXP * CAP];
__device__ float g_buf_w[NEXP * CAP];
__device__ float g_logits[NTOK * NEXP];
__device__ float g_hid[(size_t)NEXP * CAP * IDIM];
__device__ float g_shid[(size_t)NTOK * SIDIM];

// ---------------- helpers ----------------
__device__ __forceinline__ uint32_t smem_u32(const void* p) {
    uint32_t a;
    asm("{ .reg .u64 t; cvta.to.shared.u64 t, %1; cvt.u32.u64 %0, t; }" : "=r"(a) : "l"(p));
    return a;
}
__device__ __forceinline__ uint32_t pack2(float a, float b) {
    __half2 h = __floats2half2_rn(a, b);
    return *(uint32_t*)&h;
}
__device__ __forceinline__ void ldsm4(uint32_t r[4], uint32_t addr) {
    asm volatile("ldmatrix.sync.aligned.m8n8.x4.shared.b16 {%0,%1,%2,%3}, [%4];"
                 : "=r"(r[0]), "=r"(r[1]), "=r"(r[2]), "=r"(r[3]) : "r"(addr));
}
__device__ __forceinline__ void ldsm4t(uint32_t r[4], uint32_t addr) {
    asm volatile("ldmatrix.sync.aligned.m8n8.x4.trans.shared.b16 {%0,%1,%2,%3}, [%4];"
                 : "=r"(r[0]), "=r"(r[1]), "=r"(r[2]), "=r"(r[3]) : "r"(addr));
}
__device__ __forceinline__ void mma16(float c[4], const uint32_t a[4], const uint32_t b[2]) {
    asm volatile(
        "mma.sync.aligned.m16n8k16.row.col.f32.f16.f16.f32 "
        "{%0,%1,%2,%3}, {%4,%5,%6,%7}, {%8,%9}, {%0,%1,%2,%3};"
        : "+f"(c[0]), "+f"(c[1]), "+f"(c[2]), "+f"(c[3])
        : "r"(a[0]), "r"(a[1]), "r"(a[2]), "r"(a[3]), "r"(b[0]), "r"(b[1]));
}
__device__ __forceinline__ unsigned f2tf(float x) {
    unsigned y;
    asm("cvt.rna.tf32.f32 %0, %1;" : "=r"(y) : "f"(x));
    return y;
}
__device__ __forceinline__ void mma8(float c[4], const unsigned a[4], const unsigned b[2]) {
    asm volatile(
        "mma.sync.aligned.m16n8k8.row.col.f32.tf32.tf32.f32 "
        "{%0,%1,%2,%3}, {%4,%5,%6,%7}, {%8,%9}, {%0,%1,%2,%3};"
        : "+f"(c[0]), "+f"(c[1]), "+f"(c[2]), "+f"(c[3])
        : "r"(a[0]), "r"(a[1]), "r"(a[2]), "r"(a[3]), "r"(b[0]), "r"(b[1]));
}
__device__ __forceinline__ float silu_f(float v) { return v / (1.0f + expf(-v)); }

// ldmatrix per-lane byte offsets (see derivation in commit message):
// A / [n][k] tiles (stride RSA):  mats = (lo,klo),(hi,klo),(lo,khi),(hi,khi)
#define LM_A(lane)  (((((lane) >> 3) & 1) * 8 + ((lane) & 7)) * RSA + ((lane) >> 4) * 16)
// B non-trans [n][k]:             mats = (n+0,klo),(n+0,khi),(n+8,klo),(n+8,khi)
#define LM_BN(lane) ((((lane) >> 4) * 8 + ((lane) & 7)) * RSA + (((lane) >> 3) & 1) * 16)
// B trans [k][n] (stride RSB):    mats = (klo,n+0),(khi,n+0),(klo,n+8),(khi,n+8)
#define LM_BT(lane) (((((lane) >> 3) & 1) * 8 + ((lane) & 7)) * RSB + ((lane) >> 4) * 16)

// ================= fused SwiGLU up-projection (fp16 engine) =================
// hid = silu(A @ op(Bg)) * (A @ op(Bu)); block 128x128, 8 warps 2(M)x4(N), warp 64x32 dual.
template<int BNK, int EXPERT, int GATHER>
__global__ __launch_bounds__(NTH) void k_swiglu(
    const float* __restrict__ Abase, const float* __restrict__ Bg0,
    const float* __restrict__ Bu0, float* __restrict__ C,
    int Kd, int ldb, int ldc, long sB, long sC)
{
    __shared__ __align__(16) unsigned char smraw[6 * TSLOT];
    __shared__ int s_tok[128];

    const int tid = threadIdx.x;
    const int warp = tid >> 5, lane = tid & 31;
    const int wm = warp >> 2, wn = warp & 3;
    const int gq = lane >> 2, tq = lane & 3;
    const int m0 = blockIdx.y * 128, n0 = blockIdx.x * 128;

    int e = 0, cnt = 0x40000000;
    if (EXPERT) {
        e = blockIdx.z;
        cnt = g_counts[e];
        if (m0 >= cnt) return;
    }
    if (GATHER) {
        if (tid < 128) {
            int p = m0 + tid;
            s_tok[tid] = (p < cnt) ? g_buf_tok[e * CAP + p] : 0;
        }
        __syncthreads();
    }

    const uint32_t smb = smem_u32(smraw);

    // ---- loaders ----
    const float* pa[2];
    uint32_t stA[2];
#pragma unroll
    for (int j = 0; j < 2; j++) {
        int idx = tid + j * NTH;
        int m = idx >> 2, k4 = idx & 3;
        if (GATHER) pa[j] = Abase + (size_t)s_tok[m] * Kd + k4 * 4;
        else        pa[j] = Abase + (size_t)(m0 + m) * Kd + k4 * 4;
        stA[j] = (uint32_t)(m * RSA + k4 * 8);
    }
    const float* pg[2]; const float* pu[2];
    uint32_t stB[2];
    if (BNK) {
#pragma unroll
        for (int j = 0; j < 2; j++) {
            int idx = tid + j * NTH;
            int n = idx >> 2, k4 = idx & 3;
            pg[j] = Bg0 + (EXPERT ? (size_t)e * sB : 0) + (size_t)(n0 + n) * Kd + k4 * 4;
            pu[j] = Bu0 + (EXPERT ? (size_t)e * sB : 0) + (size_t)(n0 + n) * Kd + k4 * 4;
            stB[j] = (uint32_t)(n * RSA + k4 * 8);
        }
    } else {
        int k = tid >> 4, n8 = tid & 15;
        pg[0] = Bg0 + (EXPERT ? (size_t)e * sB : 0) + (size_t)k * ldb + n0 + n8 * 8;
        pu[0] = Bu0 + (EXPERT ? (size_t)e * sB : 0) + (size_t)k * ldb + n0 + n8 * 8;
        stB[0] = (uint32_t)(k * RSB + n8 * 16);
    }
    const long bumpB = BNK ? (long)BK : (long)BK * ldb;

    float4 ra[2], rg[2], ru[2];
    auto LDG = [&]() {
#pragma unroll
        for (int j = 0; j < 2; j++) { ra[j] = *(const float4*)pa[j]; pa[j] += BK; }
        if (BNK) {
#pragma unroll
            for (int j = 0; j < 2; j++) {
                rg[j] = *(const float4*)pg[j]; pg[j] += bumpB;
                ru[j] = *(const float4*)pu[j]; pu[j] += bumpB;
            }
        } else {
            rg[0] = *(const float4*)pg[0]; rg[1] = *(const float4*)(pg[0] + 4); pg[0] += bumpB;
            ru[0] = *(const float4*)pu[0]; ru[1] = *(const float4*)(pu[0] + 4); pu[0] += bumpB;
        }
    };
    auto STS = [&](int buf) {
        uint32_t aT = smb + buf * TSLOT;
        uint32_t gT = smb + 2 * TSLOT + buf * TSLOT;
        uint32_t uT = smb + 4 * TSLOT + buf * TSLOT;
#pragma unroll
        for (int j = 0; j < 2; j++) {
            uint2 v = make_uint2(pack2(ra[j].x, ra[j].y), pack2(ra[j].z, ra[j].w));
            asm volatile("st.shared.v2.u32 [%0], {%1, %2};" :: "r"(aT + stA[j]), "r"(v.x), "r"(v.y));
        }
        if (BNK) {
#pragma unroll
            for (int j = 0; j < 2; j++) {
                uint2 vg = make_uint2(pack2(rg[j].x, rg[j].y), pack2(rg[j].z, rg[j].w));
                asm volatile("st.shared.v2.u32 [%0], {%1, %2};" :: "r"(gT + stB[j]), "r"(vg.x), "r"(vg.y));
                uint2 vu = make_uint2(pack2(ru[j].x, ru[j].y), pack2(ru[j].z, ru[j].w));
                asm volatile("st.shared.v2.u32 [%0], {%1, %2};" :: "r"(uT + stB[j]), "r"(vu.x), "r"(vu.y));
            }
        } else {
            uint4 vg = make_uint4(pack2(rg[0].x, rg[0].y), pack2(rg[0].z, rg[0].w),
                                  pack2(rg[1].x, rg[1].y), pack2(rg[1].z, rg[1].w));
            asm volatile("st.shared.v4.u32 [%0], {%1, %2, %3, %4};"
                         :: "r"(gT + stB[0]), "r"(vg.x), "r"(vg.y), "r"(vg.z), "r"(vg.w));
            uint4 vu = make_uint4(pack2(ru[0].x, ru[0].y), pack2(ru[0].z, ru[0].w),
                                  pack2(ru[1].x, ru[1].y), pack2(ru[1].z, ru[1].w));
            asm volatile("st.shared.v4.u32 [%0], {%1, %2, %3, %4};"
                         :: "r"(uT + stB[0]), "r"(vu.x), "r"(vu.y), "r"(vu.z), "r"(vu.w));
        }
    };

    // fragment read offsets
    uint32_t aOff[4];
#pragma unroll
    for (int mt = 0; mt < 4; mt++) aOff[mt] = (uint32_t)((wm * 64 + mt * 16) * RSA) + LM_A(lane);
    uint32_t bOff[2];
#pragma unroll
    for (int p = 0; p < 2; p++)
        bOff[p] = BNK ? (uint32_t)((wn * 32 + p * 16) * RSA) + LM_BN(lane)
                      : (uint32_t)((wn * 32 + p * 16) * 2) + LM_BT(lane);

    float accg[4][4][4], accu[4][4][4];
#pragma unroll
    for (int mt = 0; mt < 4; mt++)
#pragma unroll
        for (int nt = 0; nt < 4; nt++)
#pragma unroll
            for (int r = 0; r < 4; r++) { accg[mt][nt][r] = 0.0f; accu[mt][nt][r] = 0.0f; }

    const int nslab = Kd / BK;
    LDG(); STS(0);
    __syncthreads();

    for (int s = 0; s < nslab; s++) {
        const int buf = s & 1;
        if (s + 1 < nslab) LDG();
        uint32_t aT = smb + buf * TSLOT;
        uint32_t gT = smb + 2 * TSLOT + buf * TSLOT;
        uint32_t uT = smb + 4 * TSLOT + buf * TSLOT;

        uint32_t af[4][4];
#pragma unroll
        for (int mt = 0; mt < 4; mt++) ldsm4(af[mt], aT + aOff[mt]);
        uint32_t bg[4][2], bu[4][2];
#pragma unroll
        for (int p = 0; p < 2; p++) {
            uint32_t t[4];
            if (BNK) ldsm4(t, gT + bOff[p]); else ldsm4t(t, gT + bOff[p]);
            bg[2 * p][0] = t[0]; bg[2 * p][1] = t[1];
            bg[2 * p + 1][0] = t[2]; bg[2 * p + 1][1] = t[3];
            if (BNK) ldsm4(t, uT + bOff[p]); else ldsm4t(t, uT + bOff[p]);
            bu[2 * p][0] = t[0]; bu[2 * p][1] = t[1];
            bu[2 * p + 1][0] = t[2]; bu[2 * p + 1][1] = t[3];
        }
#pragma unroll
        for (int mt = 0; mt < 4; mt++)
#pragma unroll
            for (int nt = 0; nt < 4; nt++) {
                mma16(accg[mt][nt], af[mt], bg[nt]);
                mma16(accu[mt][nt], af[mt], bu[nt]);
            }
        __syncthreads();
        if (s + 1 < nslab) {
            STS((s + 1) & 1);
            __syncthreads();
        }
    }

    // ---- epilogue: silu(g)*u ----
#pragma unroll
    for (int mt = 0; mt < 4; mt++)
#pragma unroll
        for (int nt = 0; nt < 4; nt++)
#pragma unroll
            for (int r = 0; r < 4; r++) {
                int row = wm * 64 + mt * 16 + gq + ((r & 2) ? 8 : 0);
                int col = wn * 32 + nt * 8 + tq * 2 + (r & 1);
                int gm = m0 + row;
                if (EXPERT && gm >= cnt) continue;
                float g = accg[mt][nt][r], u = accu[mt][nt][r];
                float* dst = C + (EXPERT ? (size_t)e * sC : 0);
                dst[(size_t)gm * ldc + n0 + col] = silu_f(g) * u;
            }
}

// ================= down GEMM (fp16 engine; 128x128 block, warp 64x32) =================
template<int BNK, int EXPERT, int ATOMIC>
__global__ __launch_bounds__(NTH, 2) void k_gemm(
    const float* __restrict__ Abase, const float* __restrict__ Bbase,
    float* __restrict__ C, int Kd, int ldb, int ldc,
    long sA, long sB)
{
    __shared__ __align__(16) unsigned char smraw[4 * TSLOT];
    __shared__ int   s_tok[128];
    __shared__ float s_w[128];

    const int tid = threadIdx.x;
    const int warp = tid >> 5, lane = tid & 31;
    const int wm = warp >> 2, wn = warp & 3;
    const int gq = lane >> 2, tq = lane & 3;
    const int m0 = blockIdx.y * 128, n0 = blockIdx.x * 128;

    int e = 0, cnt = 0x40000000;
    if (EXPERT) {
        e = blockIdx.z;
        cnt = g_counts[e];
        if (m0 >= cnt) return;
    }
    if (ATOMIC) {
        if (tid < 128) {
            int p = m0 + tid;
            int ok = (p < cnt);
            s_tok[tid] = ok ? g_buf_tok[e * CAP + p] : 0;
            s_w[tid]   = ok ? g_buf_w[e * CAP + p] : 0.0f;
        }
        __syncthreads();
    }

    const uint32_t smb = smem_u32(smraw);

    const float* pa[2];
    uint32_t stA[2];
#pragma unroll
    for (int j = 0; j < 2; j++) {
        int idx = tid + j * NTH;
        int m = idx >> 2, k4 = idx & 3;
        pa[j] = Abase + (EXPERT ? (size_t)e * sA : 0) + (size_t)(m0 + m) * Kd + k4 * 4;
        stA[j] = (uint32_t)(m * RSA + k4 * 8);
    }
    const float* pb[2];
    uint32_t stB[2];
    if (BNK) {
#pragma unroll
        for (int j = 0; j < 2; j++) {
            int idx = tid + j * NTH;
            int n = idx >> 2, k4 = idx & 3;
            pb[j] = Bbase + (EXPERT ? (size_t)e * sB : 0) + (size_t)(n0 + n) * Kd + k4 * 4;
            stB[j] = (uint32_t)(n * RSA + k4 * 8);
        }
    } else {
        int k = tid >> 4, n8 = tid & 15;
        pb[0] = Bbase + (EXPERT ? (size_t)e * sB : 0) + (size_t)k * ldb + n0 + n8 * 8;
        stB[0] = (uint32_t)(k * RSB + n8 * 16);
    }
    const long bumpB = BNK ? (long)BK : (long)BK * ldb;

    float4 ra[2], rb[2];
    auto LDG = [&]() {
#pragma unroll
        for (int j = 0; j < 2; j++) { ra[j] = *(const float4*)pa[j]; pa[j] += BK; }
        if (BNK) {
#pragma unroll
            for (int j = 0; j < 2; j++) { rb[j] = *(const float4*)pb[j]; pb[j] += bumpB; }
        } else {
            rb[0] = *(const float4*)pb[0]; rb[1] = *(const float4*)(pb[0] + 4); pb[0] += bumpB;
        }
    };
    auto STS = [&](int buf) {
        uint32_t aT = smb + buf * TSLOT;
        uint32_t bT = smb + 2 * TSLOT + buf * TSLOT;
#pragma unroll
        for (int j = 0; j < 2; j++) {
            uint2 v = make_uint2(pack2(ra[j].x, ra[j].y), pack2(ra[j].z, ra[j].w));
            asm volatile("st.shared.v2.u32 [%0], {%1, %2};" :: "r"(aT + stA[j]), "r"(v.x), "r"(v.y));
        }
        if (BNK) {
#pragma unroll
            for (int j = 0; j < 2; j++) {
                uint2 v = make_uint2(pack2(rb[j].x, rb[j].y), pack2(rb[j].z, rb[j].w));
                asm volatile("st.shared.v2.u32 [%0], {%1, %2};" :: "r"(bT + stB[j]), "r"(v.x), "r"(v.y));
            }
        } else {
            uint4 v = make_uint4(pack2(rb[0].x, rb[0].y), pack2(rb[0].z, rb[0].w),
                                 pack2(rb[1].x, rb[1].y), pack2(rb[1].z, rb[1].w));
            asm volatile("st.shared.v4.u32 [%0], {%1, %2, %3, %4};"
                         :: "r"(bT + stB[0]), "r"(v.x), "r"(v.y), "r"(v.z), "r"(v.w));
        }
    };

    uint32_t aOff[4];
#pragma unroll
    for (int mt = 0; mt < 4; mt++) aOff[mt] = (uint32_t)((wm * 64 + mt * 16) * RSA) + LM_A(lane);
    uint32_t bOff[2];
#pragma unroll
    for (int p = 0; p < 2; p++)
        bOff[p] = BNK ? (uint32_t)((wn * 32 + p * 16) * RSA) + LM_BN(lane)
                      : (uint32_t)((wn * 32 + p * 16) * 2) + LM_BT(lane);

    float acc[4][4][4];
#pragma unroll
    for (int mt = 0; mt < 4; mt++)
#pragma unroll
        for (int nt = 0; nt < 4; nt++)
#pragma unroll
            for (int r = 0; r < 4; r++) acc[mt][nt][r] = 0.0f;

    const int nslab = Kd / BK;
    LDG(); STS(0);
    __syncthreads();

    for (int s = 0; s < nslab; s++) {
        const int buf = s & 1;
        if (s + 1 < nslab) LDG();
        uint32_t aT = smb + buf * TSLOT;
        uint32_t bT = smb + 2 * TSLOT + buf * TSLOT;

        uint32_t af[4][4];
#pragma unroll
        for (int mt = 0; mt < 4; mt++) ldsm4(af[mt], aT + aOff[mt]);
        uint32_t bf[4][2];
#pragma unroll
        for (int p = 0; p < 2; p++) {
            uint32_t t[4];
            if (BNK) ldsm4(t, bT + bOff[p]); else ldsm4t(t, bT + bOff[p]);
            bf[2 * p][0] = t[0]; bf[2 * p][1] = t[1];
            bf[2 * p + 1][0] = t[2]; bf[2 * p + 1][1] = t[3];
        }
#pragma unroll
        for (int mt = 0; mt < 4; mt++)
#pragma unroll
            for (int nt = 0; nt < 4; nt++)
                mma16(acc[mt][nt], af[mt], bf[nt]);
        __syncthreads();
        if (s + 1 < nslab) {
            STS((s + 1) & 1);
            __syncthreads();
        }
    }

#pragma unroll
    for (int mt = 0; mt < 4; mt++)
#pragma unroll
        for (int nt = 0; nt < 4; nt++)
#pragma unroll
            for (int r = 0; r < 4; r++) {
                int row = wm * 64 + mt * 16 + gq + ((r & 2) ? 8 : 0);
                int col = wn * 32 + nt * 8 + tq * 2 + (r & 1);
                int gm = m0 + row;
                if (EXPERT && gm >= cnt) continue;
                if (ATOMIC) {
                    atomicAdd(&C[(size_t)s_tok[row] * ldc + n0 + col],
                              acc[mt][nt][r] * s_w[row]);
                } else {
                    C[(size_t)gm * ldc + n0 + col] = acc[mt][nt][r];
                }
            }
}

// ================= router logits: 3xTF32 (near-fp32, exact top-k) =================
#define RTH 128
__global__ __launch_bounds__(RTH) void k_router_gemm(const float* __restrict__ A,
                                                     const float* __restrict__ B,
                                                     float* __restrict__ C) {
    __shared__ float As[16][64 + 4];
    __shared__ float Bsm[16][64 + 4];
    int tid = threadIdx.x;
    int warp = tid >> 5, lane = tid & 31;
    int wm = warp >> 1, wn = warp & 1, gq = lane >> 2, tq = lane & 3;
    int m0 = blockIdx.y * 64;

    const float* Ab = A + (size_t)m0 * HDIM;
    const float* Bb = B;

    float acc[2][4][4];
#pragma unroll
    for (int mt = 0; mt < 2; mt++)
#pragma unroll
        for (int nt = 0; nt < 4; nt++)
#pragma unroll
            for (int r = 0; r < 4; r++) acc[mt][nt][r] = 0.0f;

    for (int k0 = 0; k0 < HDIM; k0 += 16) {
        __syncthreads();
#pragma unroll
        for (int j = 0; j < 2; j++) {
            int it = tid + j * RTH;
            int r = it >> 2, c4 = it & 3;
            float4 va = *(const float4*)(Ab + (size_t)r * HDIM + k0 + c4 * 4);
            As[c4 * 4 + 0][r] = va.x; As[c4 * 4 + 1][r] = va.y;
            As[c4 * 4 + 2][r] = va.z; As[c4 * 4 + 3][r] = va.w;
            float4 vb = *(const float4*)(Bb + (size_t)r * HDIM + k0 + c4 * 4);
            Bsm[c4 * 4 + 0][r] = vb.x; Bsm[c4 * 4 + 1][r] = vb.y;
            Bsm[c4 * 4 + 2][r] = vb.z; Bsm[c4 * 4 + 3][r] = vb.w;
        }
        __syncthreads();
#pragma unroll
        for (int kk = 0; kk < 16; kk += 8) {
            float af[2][4], bfv[4][2];
#pragma unroll
            for (int mt = 0; mt < 2; mt++) {
                int rb = wm * 32 + mt * 16;
                af[mt][0] = As[kk + tq    ][rb + gq    ];
                af[mt][1] = As[kk + tq    ][rb + gq + 8];
                af[mt][2] = As[kk + tq + 4][rb + gq    ];
                af[mt][3] = As[kk + tq + 4][rb + gq + 8];
            }
#pragma unroll
            for (int nt = 0; nt < 4; nt++) {
                int cb = wn * 32 + nt * 8 + gq;
                bfv[nt][0] = Bsm[kk + tq    ][cb];
                bfv[nt][1] = Bsm[kk + tq + 4][cb];
            }
            unsigned ah[2][4], al[2][4], bh[4][2], bl[4][2];
#pragma unroll
            for (int mt = 0; mt < 2; mt++)
#pragma unroll
                for (int i = 0; i < 4; i++) {
                    ah[mt][i] = f2tf(af[mt][i]);
                    al[mt][i] = f2tf(af[mt][i] - __uint_as_float(ah[mt][i]));
                }
#pragma unroll
            for (int nt = 0; nt < 4; nt++)
#pragma unroll
                for (int i = 0; i < 2; i++) {
                    bh[nt][i] = f2tf(bfv[nt][i]);
                    bl[nt][i] = f2tf(bfv[nt][i] - __uint_as_float(bh[nt][i]));
                }
#pragma unroll
            for (int mt = 0; mt < 2; mt++)
#pragma unroll
                for (int nt = 0; nt < 4; nt++) {
                    mma8(acc[mt][nt], al[mt], bh[nt]);
                    mma8(acc[mt][nt], ah[mt], bl[nt]);
                    mma8(acc[mt][nt], ah[mt], bh[nt]);
                }
        }
    }
#pragma unroll
    for (int mt = 0; mt < 2; mt++)
#pragma unroll
        for (int nt = 0; nt < 4; nt++)
#pragma unroll
            for (int r = 0; r < 4; r++) {
                int row = wm * 32 + mt * 16 + gq + ((r & 2) ? 8 : 0);
                int col = wn * 32 + nt * 8 + tq * 2 + (r & 1);
                C[(size_t)(m0 + row) * NEXP + col] = acc[mt][nt][r];
            }
}

// ================= router softmax + top-6 + dispatch =================
__global__ void k_init() {
    if (threadIdx.x < NEXP) g_counts[threadIdx.x] = 0;
}

__global__ void k_router() {
    int warp = threadIdx.x >> 5, lane = threadIdx.x & 31;
    int t = blockIdx.x * 8 + warp;
    float v0 = g_logits[t * NEXP + lane];
    float v1 = g_logits[t * NEXP + 32 + lane];
    float m = fmaxf(v0, v1);
#pragma unroll
    for (int s = 16; s > 0; s >>= 1) m = fmaxf(m, __shfl_xor_sync(0xffffffffu, m, s));
    float e0 = expf(v0 - m), e1 = expf(v1 - m);
    float sum = e0 + e1;
#pragma unroll
    for (int s = 16; s > 0; s >>= 1) sum += __shfl_xor_sync(0xffffffffu, sum, s);
    float inv = 1.0f / sum;
    float p0 = e0 * inv, p1 = e1 * inv;

#pragma unroll
    for (int k = 0; k < TOPK; k++) {
        float bv; int bi;
        if (p0 >= p1) { bv = p0; bi = lane; } else { bv = p1; bi = lane + 32; }
#pragma unroll
        for (int s = 16; s > 0; s >>= 1) {
            float ov = __shfl_xor_sync(0xffffffffu, bv, s);
            int   oi = __shfl_xor_sync(0xffffffffu, bi, s);
            if (ov > bv || (ov == bv && oi < bi)) { bv = ov; bi = oi; }
        }
        if (lane == 0) {
            int pos = atomicAdd(&g_counts[bi], 1);
            if (pos < CAP) {
                g_buf_tok[bi * CAP + pos] = t;
                g_buf_w[bi * CAP + pos] = bv;
            }
        }
        if (bi < 32) { if (lane == bi) p0 = -1.0f; }
        else         { if (lane == bi - 32) p1 = -1.0f; }
    }
}

// ================= launch =================
extern "C" void kernel_launch(void* const* d_in, const int* in_sizes, int n_in,
                              void* d_out, int out_size) {
    const float* x   = (const float*)d_in[0];
    const float* gw  = (const float*)d_in[1];
    const float* gup = (const float*)d_in[2];
    const float* dwn = (const float*)d_in[3];
    const float* sgw = (const float*)d_in[4];
    const float* suw = (const float*)d_in[5];
    const float* sdw = (const float*)d_in[6];
    float* out = (float*)d_out;

    float *p_logits, *p_hid, *p_shid;
    cudaGetSymbolAddress((void**)&p_logits, g_logits);
    cudaGetSymbolAddress((void**)&p_hid,  g_hid);
    cudaGetSymbolAddress((void**)&p_shid, g_shid);

    k_init<<<1, 64>>>();
    // router: near-fp32 logits so top-k matches reference exactly
    k_router_gemm<<<dim3(1, NTOK / 64), RTH>>>(x, gw, p_logits);
    k_router<<<NTOK / 8, 256>>>();

    // shared experts: fused SwiGLU up ([N,K] weights), then down -> out (plain store covers out)
    k_swiglu<1,0,0><<<dim3(SIDIM / 128, NTOK / 128), NTH>>>(
        x, sgw, suw, p_shid, HDIM, 0, SIDIM, 0, 0);
    k_gemm<1,0,0><<<dim3(HDIM / 128, NTOK / 128), NTH>>>(
        p_shid, sdw, out, SIDIM, 0, HDIM, 0, 0);

    // routed experts: fused SwiGLU gate_up (gathered A, [K,N] weights), down (atomic scatter-add)
    k_swiglu<0,1,1><<<dim3(IDIM / 128, CAP / 128, NEXP), NTH>>>(
        x, gup, gup + IDIM, p_hid, HDIM, TWOI, IDIM, (long)HDIM * TWOI, (long)CAP * IDIM);
    k_gemm<0,1,1><<<dim3(HDIM / 128, CAP / 128, NEXP), NTH>>>(
        p_hid, dwn, out, IDIM, HDIM, HDIM, (long)CAP * IDIM, (long)IDIM * HDIM);
}

// round 9
// speedup vs baseline: 1.4711x; 1.1576x over previous
#include <cuda_runtime.h>
#include <cuda_fp16.h>
#include <math.h>
#include <stdint.h>

// ---------------- problem constants ----------------
#define NTOK   2048
#define NEXP   64
#define TOPK   6
#define CAP    512
#define HDIM   2048
#define IDIM   768
#define TWOI   1536
#define SIDIM  1536

// ---------------- tile config ----------------
#define BK   16              // k per slab (halfs)
#define NTH  256             // 8 warps
#define RSA  48              // [row][k] tile row stride BYTES (16 halfs + 8 pad)
#define RSB  272             // [k][n] tile row stride BYTES (128 halfs + 8 pad)
#define TSLOT 6144           // bytes per tile slot (A:128*48; B-kn:16*272=4352 fits)
#define SWIGLU_SMEM (9 * TSLOT)   // 3 stages x (A,G,U) = 55296 B (dynamic)

// ---------------- scratch ----------------
__device__ int   g_counts[NEXP];
__device__ int   g_buf_tok[NEXP * CAP];
__device__ float g_buf_w[NEXP * CAP];
__device__ float g_logits[NTOK * NEXP];
__device__ float g_hid[(size_t)NEXP * CAP * IDIM];
__device__ float g_shid[(size_t)NTOK * SIDIM];

// ---------------- helpers ----------------
__device__ __forceinline__ uint32_t smem_u32(const void* p) {
    uint32_t a;
    asm("{ .reg .u64 t; cvta.to.shared.u64 t, %1; cvt.u32.u64 %0, t; }" : "=r"(a) : "l"(p));
    return a;
}
__device__ __forceinline__ uint32_t pack2(float a, float b) {
    __half2 h = __floats2half2_rn(a, b);
    return *(uint32_t*)&h;
}
__device__ __forceinline__ void ldsm4(uint32_t r[4], uint32_t addr) {
    asm volatile("ldmatrix.sync.aligned.m8n8.x4.shared.b16 {%0,%1,%2,%3}, [%4];"
                 : "=r"(r[0]), "=r"(r[1]), "=r"(r[2]), "=r"(r[3]) : "r"(addr));
}
__device__ __forceinline__ void ldsm4t(uint32_t r[4], uint32_t addr) {
    asm volatile("ldmatrix.sync.aligned.m8n8.x4.trans.shared.b16 {%0,%1,%2,%3}, [%4];"
                 : "=r"(r[0]), "=r"(r[1]), "=r"(r[2]), "=r"(r[3]) : "r"(addr));
}
__device__ __forceinline__ void mma16(float c[4], const uint32_t a[4], const uint32_t b[2]) {
    asm volatile(
        "mma.sync.aligned.m16n8k16.row.col.f32.f16.f16.f32 "
        "{%0,%1,%2,%3}, {%4,%5,%6,%7}, {%8,%9}, {%0,%1,%2,%3};"
        : "+f"(c[0]), "+f"(c[1]), "+f"(c[2]), "+f"(c[3])
        : "r"(a[0]), "r"(a[1]), "r"(a[2]), "r"(a[3]), "r"(b[0]), "r"(b[1]));
}
__device__ __forceinline__ unsigned f2tf(float x) {
    unsigned y;
    asm("cvt.rna.tf32.f32 %0, %1;" : "=r"(y) : "f"(x));
    return y;
}
__device__ __forceinline__ void mma8(float c[4], const unsigned a[4], const unsigned b[2]) {
    asm volatile(
        "mma.sync.aligned.m16n8k8.row.col.f32.tf32.tf32.f32 "
        "{%0,%1,%2,%3}, {%4,%5,%6,%7}, {%8,%9}, {%0,%1,%2,%3};"
        : "+f"(c[0]), "+f"(c[1]), "+f"(c[2]), "+f"(c[3])
        : "r"(a[0]), "r"(a[1]), "r"(a[2]), "r"(a[3]), "r"(b[0]), "r"(b[1]));
}
__device__ __forceinline__ float silu_f(float v) { return v / (1.0f + expf(-v)); }

// ldmatrix per-lane byte offsets:
// A / [n][k] tiles (stride RSA):  mats = (lo,klo),(hi,klo),(lo,khi),(hi,khi)
#define LM_A(lane)  (((((lane) >> 3) & 1) * 8 + ((lane) & 7)) * RSA + ((lane) >> 4) * 16)
// B non-trans [n][k]:             mats = (n+0,klo),(n+0,khi),(n+8,klo),(n+8,khi)
#define LM_BN(lane) ((((lane) >> 4) * 8 + ((lane) & 7)) * RSA + (((lane) >> 3) & 1) * 16)
// B trans [k][n] (stride RSB):    mats = (klo,n+0),(khi,n+0),(klo,n+8),(khi,n+8)
#define LM_BT(lane) (((((lane) >> 3) & 1) * 8 + ((lane) & 7)) * RSB + ((lane) >> 4) * 16)

// ================= fused SwiGLU up-projection (fp16, 3-stage pipeline) =================
template<int BNK, int EXPERT, int GATHER>
__global__ __launch_bounds__(NTH) void k_swiglu(
    const float* __restrict__ Abase, const float* __restrict__ Bg0,
    const float* __restrict__ Bu0, float* __restrict__ C,
    int Kd, int ldb, int ldc, long sB, long sC)
{
    extern __shared__ __align__(16) unsigned char smraw[];
    __shared__ int s_tok[128];

    const int tid = threadIdx.x;
    const int warp = tid >> 5, lane = tid & 31;
    const int wm = warp >> 2, wn = warp & 3;
    const int gq = lane >> 2, tq = lane & 3;
    const int m0 = blockIdx.y * 128, n0 = blockIdx.x * 128;

    int e = 0, cnt = 0x40000000;
    if (EXPERT) {
        e = blockIdx.z;
        cnt = g_counts[e];
        if (m0 >= cnt) return;
    }
    if (GATHER) {
        if (tid < 128) {
            int p = m0 + tid;
            s_tok[tid] = (p < cnt) ? g_buf_tok[e * CAP + p] : 0;
        }
        __syncthreads();
    }

    const uint32_t smb = smem_u32(smraw);

    // ---- loaders ----
    const float* pa[2];
    uint32_t stA[2];
#pragma unroll
    for (int j = 0; j < 2; j++) {
        int idx = tid + j * NTH;
        int m = idx >> 2, k4 = idx & 3;
        if (GATHER) pa[j] = Abase + (size_t)s_tok[m] * Kd + k4 * 4;
        else        pa[j] = Abase + (size_t)(m0 + m) * Kd + k4 * 4;
        stA[j] = (uint32_t)(m * RSA + k4 * 8);
    }
    const float* pg[2]; const float* pu[2];
    uint32_t stB[2];
    if (BNK) {
#pragma unroll
        for (int j = 0; j < 2; j++) {
            int idx = tid + j * NTH;
            int n = idx >> 2, k4 = idx & 3;
            pg[j] = Bg0 + (EXPERT ? (size_t)e * sB : 0) + (size_t)(n0 + n) * Kd + k4 * 4;
            pu[j] = Bu0 + (EXPERT ? (size_t)e * sB : 0) + (size_t)(n0 + n) * Kd + k4 * 4;
            stB[j] = (uint32_t)(n * RSA + k4 * 8);
        }
    } else {
        int k = tid >> 4, n8 = tid & 15;
        pg[0] = Bg0 + (EXPERT ? (size_t)e * sB : 0) + (size_t)k * ldb + n0 + n8 * 8;
        pu[0] = Bu0 + (EXPERT ? (size_t)e * sB : 0) + (size_t)k * ldb + n0 + n8 * 8;
        stB[0] = (uint32_t)(k * RSB + n8 * 16);
    }
    const long bumpB = BNK ? (long)BK : (long)BK * ldb;

    float4 ra[2], rg[2], ru[2];
    auto LDG = [&]() {
#pragma unroll
        for (int j = 0; j < 2; j++) { ra[j] = *(const float4*)pa[j]; pa[j] += BK; }
        if (BNK) {
#pragma unroll
            for (int j = 0; j < 2; j++) {
                rg[j] = *(const float4*)pg[j]; pg[j] += bumpB;
                ru[j] = *(const float4*)pu[j]; pu[j] += bumpB;
            }
        } else {
            rg[0] = *(const float4*)pg[0]; rg[1] = *(const float4*)(pg[0] + 4); pg[0] += bumpB;
            ru[0] = *(const float4*)pu[0]; ru[1] = *(const float4*)(pu[0] + 4); pu[0] += bumpB;
        }
    };
    auto STS = [&](int buf) {
        uint32_t aT = smb + buf * TSLOT;
        uint32_t gT = smb + 3 * TSLOT + buf * TSLOT;
        uint32_t uT = smb + 6 * TSLOT + buf * TSLOT;
#pragma unroll
        for (int j = 0; j < 2; j++) {
            uint2 v = make_uint2(pack2(ra[j].x, ra[j].y), pack2(ra[j].z, ra[j].w));
            asm volatile("st.shared.v2.u32 [%0], {%1, %2};" :: "r"(aT + stA[j]), "r"(v.x), "r"(v.y));
        }
        if (BNK) {
#pragma unroll
            for (int j = 0; j < 2; j++) {
                uint2 vg = make_uint2(pack2(rg[j].x, rg[j].y), pack2(rg[j].z, rg[j].w));
                asm volatile("st.shared.v2.u32 [%0], {%1, %2};" :: "r"(gT + stB[j]), "r"(vg.x), "r"(vg.y));
                uint2 vu = make_uint2(pack2(ru[j].x, ru[j].y), pack2(ru[j].z, ru[j].w));
                asm volatile("st.shared.v2.u32 [%0], {%1, %2};" :: "r"(uT + stB[j]), "r"(vu.x), "r"(vu.y));
            }
        } else {
            uint4 vg = make_uint4(pack2(rg[0].x, rg[0].y), pack2(rg[0].z, rg[0].w),
                                  pack2(rg[1].x, rg[1].y), pack2(rg[1].z, rg[1].w));
            asm volatile("st.shared.v4.u32 [%0], {%1, %2, %3, %4};"
                         :: "r"(gT + stB[0]), "r"(vg.x), "r"(vg.y), "r"(vg.z), "r"(vg.w));
            uint4 vu = make_uint4(pack2(ru[0].x, ru[0].y), pack2(ru[0].z, ru[0].w),
                                  pack2(ru[1].x, ru[1].y), pack2(ru[1].z, ru[1].w));
            asm volatile("st.shared.v4.u32 [%0], {%1, %2, %3, %4};"
                         :: "r"(uT + stB[0]), "r"(vu.x), "r"(vu.y), "r"(vu.z), "r"(vu.w));
        }
    };

    uint32_t aOff[4];
#pragma unroll
    for (int mt = 0; mt < 4; mt++) aOff[mt] = (uint32_t)((wm * 64 + mt * 16) * RSA) + LM_A(lane);
    uint32_t bOff[2];
#pragma unroll
    for (int p = 0; p < 2; p++)
        bOff[p] = BNK ? (uint32_t)((wn * 32 + p * 16) * RSA) + LM_BN(lane)
                      : (uint32_t)((wn * 32 + p * 16) * 2) + LM_BT(lane);

    float accg[4][4][4], accu[4][4][4];
#pragma unroll
    for (int mt = 0; mt < 4; mt++)
#pragma unroll
        for (int nt = 0; nt < 4; nt++)
#pragma unroll
            for (int r = 0; r < 4; r++) { accg[mt][nt][r] = 0.0f; accu[mt][nt][r] = 0.0f; }

    const int nslab = Kd / BK;
    // ---- 3-stage prologue ----
    LDG(); STS(0);
    LDG(); STS(1);
    __syncthreads();

    int bc = 0, bs = 2;
    for (int s = 0; s < nslab; s++) {
        const bool pf = (s + 2 < nslab);
        if (pf) LDG();                       // slab s+2 into staging regs
        uint32_t aT = smb + bc * TSLOT;
        uint32_t gT = smb + 3 * TSLOT + bc * TSLOT;
        uint32_t uT = smb + 6 * TSLOT + bc * TSLOT;

        uint32_t af[4][4];
#pragma unroll
        for (int mt = 0; mt < 4; mt++) ldsm4(af[mt], aT + aOff[mt]);
        uint32_t bg[4][2], bu[4][2];
#pragma unroll
        for (int p = 0; p < 2; p++) {
            uint32_t t[4];
            if (BNK) ldsm4(t, gT + bOff[p]); else ldsm4t(t, gT + bOff[p]);
            bg[2 * p][0] = t[0]; bg[2 * p][1] = t[1];
            bg[2 * p + 1][0] = t[2]; bg[2 * p + 1][1] = t[3];
            if (BNK) ldsm4(t, uT + bOff[p]); else ldsm4t(t, uT + bOff[p]);
            bu[2 * p][0] = t[0]; bu[2 * p][1] = t[1];
            bu[2 * p + 1][0] = t[2]; bu[2 * p + 1][1] = t[3];
        }
#pragma unroll
        for (int mt = 0; mt < 4; mt++)
#pragma unroll
            for (int nt = 0; nt < 4; nt++) {
                mma16(accg[mt][nt], af[mt], bg[nt]);
                mma16(accu[mt][nt], af[mt], bu[nt]);
            }
        __syncthreads();
        if (pf) STS(bs);                     // overlaps next slab's compute
        bc = (bc == 2) ? 0 : bc + 1;
        bs = (bs == 2) ? 0 : bs + 1;
    }

    // ---- epilogue: silu(g)*u ----
#pragma unroll
    for (int mt = 0; mt < 4; mt++)
#pragma unroll
        for (int nt = 0; nt < 4; nt++)
#pragma unroll
            for (int r = 0; r < 4; r++) {
                int row = wm * 64 + mt * 16 + gq + ((r & 2) ? 8 : 0);
                int col = wn * 32 + nt * 8 + tq * 2 + (r & 1);
                int gm = m0 + row;
                if (EXPERT && gm >= cnt) continue;
                float g = accg[mt][nt][r], u = accu[mt][nt][r];
                float* dst = C + (EXPERT ? (size_t)e * sC : 0);
                dst[(size_t)gm * ldc + n0 + col] = silu_f(g) * u;
            }
}

// ================= down GEMM (fp16, 3-stage pipeline; 128x128 block) =================
template<int BNK, int EXPERT, int ATOMIC>
__global__ __launch_bounds__(NTH, 2) void k_gemm(
    const float* __restrict__ Abase, const float* __restrict__ Bbase,
    float* __restrict__ C, int Kd, int ldb, int ldc,
    long sA, long sB)
{
    __shared__ __align__(16) unsigned char smraw[6 * TSLOT];   // 36 KB static
    __shared__ int   s_tok[128];
    __shared__ float s_w[128];

    const int tid = threadIdx.x;
    const int warp = tid >> 5, lane = tid & 31;
    const int wm = warp >> 2, wn = warp & 3;
    const int gq = lane >> 2, tq = lane & 3;
    const int m0 = blockIdx.y * 128, n0 = blockIdx.x * 128;

    int e = 0, cnt = 0x40000000;
    if (EXPERT) {
        e = blockIdx.z;
        cnt = g_counts[e];
        if (m0 >= cnt) return;
    }
    if (ATOMIC) {
        if (tid < 128) {
            int p = m0 + tid;
            int ok = (p < cnt);
            s_tok[tid] = ok ? g_buf_tok[e * CAP + p] : 0;
            s_w[tid]   = ok ? g_buf_w[e * CAP + p] : 0.0f;
        }
        __syncthreads();
    }

    const uint32_t smb = smem_u32(smraw);

    const float* pa[2];
    uint32_t stA[2];
#pragma unroll
    for (int j = 0; j < 2; j++) {
        int idx = tid + j * NTH;
        int m = idx >> 2, k4 = idx & 3;
        pa[j] = Abase + (EXPERT ? (size_t)e * sA : 0) + (size_t)(m0 + m) * Kd + k4 * 4;
        stA[j] = (uint32_t)(m * RSA + k4 * 8);
    }
    const float* pb[2];
    uint32_t stB[2];
    if (BNK) {
#pragma unroll
        for (int j = 0; j < 2; j++) {
            int idx = tid + j * NTH;
            int n = idx >> 2, k4 = idx & 3;
            pb[j] = Bbase + (EXPERT ? (size_t)e * sB : 0) + (size_t)(n0 + n) * Kd + k4 * 4;
            stB[j] = (uint32_t)(n * RSA + k4 * 8);
        }
    } else {
        int k = tid >> 4, n8 = tid & 15;
        pb[0] = Bbase + (EXPERT ? (size_t)e * sB : 0) + (size_t)k * ldb + n0 + n8 * 8;
        stB[0] = (uint32_t)(k * RSB + n8 * 16);
    }
    const long bumpB = BNK ? (long)BK : (long)BK * ldb;

    float4 ra[2], rb[2];
    auto LDG = [&]() {
#pragma unroll
        for (int j = 0; j < 2; j++) { ra[j] = *(const float4*)pa[j]; pa[j] += BK; }
        if (BNK) {
#pragma unroll
            for (int j = 0; j < 2; j++) { rb[j] = *(const float4*)pb[j]; pb[j] += bumpB; }
        } else {
            rb[0] = *(const float4*)pb[0]; rb[1] = *(const float4*)(pb[0] + 4); pb[0] += bumpB;
        }
    };
    auto STS = [&](int buf) {
        uint32_t aT = smb + buf * TSLOT;
        uint32_t bT = smb + 3 * TSLOT + buf * TSLOT;
#pragma unroll
        for (int j = 0; j < 2; j++) {
            uint2 v = make_uint2(pack2(ra[j].x, ra[j].y), pack2(ra[j].z, ra[j].w));
            asm volatile("st.shared.v2.u32 [%0], {%1, %2};" :: "r"(aT + stA[j]), "r"(v.x), "r"(v.y));
        }
        if (BNK) {
#pragma unroll
            for (int j = 0; j < 2; j++) {
                uint2 v = make_uint2(pack2(rb[j].x, rb[j].y), pack2(rb[j].z, rb[j].w));
                asm volatile("st.shared.v2.u32 [%0], {%1, %2};" :: "r"(bT + stB[j]), "r"(v.x), "r"(v.y));
            }
        } else {
            uint4 v = make_uint4(pack2(rb[0].x, rb[0].y), pack2(rb[0].z, rb[0].w),
                                 pack2(rb[1].x, rb[1].y), pack2(rb[1].z, rb[1].w));
            asm volatile("st.shared.v4.u32 [%0], {%1, %2, %3, %4};"
                         :: "r"(bT + stB[0]), "r"(v.x), "r"(v.y), "r"(v.z), "r"(v.w));
        }
    };

    uint32_t aOff[4];
#pragma unroll
    for (int mt = 0; mt < 4; mt++) aOff[mt] = (uint32_t)((wm * 64 + mt * 16) * RSA) + LM_A(lane);
    uint32_t bOff[2];
#pragma unroll
    for (int p = 0; p < 2; p++)
        bOff[p] = BNK ? (uint32_t)((wn * 32 + p * 16) * RSA) + LM_BN(lane)
                      : (uint32_t)((wn * 32 + p * 16) * 2) + LM_BT(lane);

    float acc[4][4][4];
#pragma unroll
    for (int mt = 0; mt < 4; mt++)
#pragma unroll
        for (int nt = 0; nt < 4; nt++)
#pragma unroll
            for (int r = 0; r < 4; r++) acc[mt][nt][r] = 0.0f;

    const int nslab = Kd / BK;
    LDG(); STS(0);
    LDG(); STS(1);
    __syncthreads();

    int bc = 0, bs = 2;
    for (int s = 0; s < nslab; s++) {
        const bool pf = (s + 2 < nslab);
        if (pf) LDG();
        uint32_t aT = smb + bc * TSLOT;
        uint32_t bT = smb + 3 * TSLOT + bc * TSLOT;

        uint32_t af[4][4];
#pragma unroll
        for (int mt = 0; mt < 4; mt++) ldsm4(af[mt], aT + aOff[mt]);
        uint32_t bf[4][2];
#pragma unroll
        for (int p = 0; p < 2; p++) {
            uint32_t t[4];
            if (BNK) ldsm4(t, bT + bOff[p]); else ldsm4t(t, bT + bOff[p]);
            bf[2 * p][0] = t[0]; bf[2 * p][1] = t[1];
            bf[2 * p + 1][0] = t[2]; bf[2 * p + 1][1] = t[3];
        }
#pragma unroll
        for (int mt = 0; mt < 4; mt++)
#pragma unroll
            for (int nt = 0; nt < 4; nt++)
                mma16(acc[mt][nt], af[mt], bf[nt]);
        __syncthreads();
        if (pf) STS(bs);
        bc = (bc == 2) ? 0 : bc + 1;
        bs = (bs == 2) ? 0 : bs + 1;
    }

#pragma unroll
    for (int mt = 0; mt < 4; mt++)
#pragma unroll
        for (int nt = 0; nt < 4; nt++)
#pragma unroll
            for (int r = 0; r < 4; r++) {
                int row = wm * 64 + mt * 16 + gq + ((r & 2) ? 8 : 0);
                int col = wn * 32 + nt * 8 + tq * 2 + (r & 1);
                int gm = m0 + row;
                if (EXPERT && gm >= cnt) continue;
                if (ATOMIC) {
                    atomicAdd(&C[(size_t)s_tok[row] * ldc + n0 + col],
                              acc[mt][nt][r] * s_w[row]);
                } else {
                    C[(size_t)gm * ldc + n0 + col] = acc[mt][nt][r];
                }
            }
}

// ================= router logits: 3xTF32 (near-fp32, exact top-k) =================
#define RTH 128
__global__ __launch_bounds__(RTH) void k_router_gemm(const float* __restrict__ A,
                                                     const float* __restrict__ B,
                                                     float* __restrict__ C) {
    __shared__ float As[16][64 + 4];
    __shared__ float Bsm[16][64 + 4];
    int tid = threadIdx.x;
    int warp = tid >> 5, lane = tid & 31;
    int wm = warp >> 1, wn = warp & 1, gq = lane >> 2, tq = lane & 3;
    int m0 = blockIdx.y * 64;

    const float* Ab = A + (size_t)m0 * HDIM;
    const float* Bb = B;

    float acc[2][4][4];
#pragma unroll
    for (int mt = 0; mt < 2; mt++)
#pragma unroll
        for (int nt = 0; nt < 4; nt++)
#pragma unroll
            for (int r = 0; r < 4; r++) acc[mt][nt][r] = 0.0f;

    for (int k0 = 0; k0 < HDIM; k0 += 16) {
        __syncthreads();
#pragma unroll
        for (int j = 0; j < 2; j++) {
            int it = tid + j * RTH;
            int r = it >> 2, c4 = it & 3;
            float4 va = *(const float4*)(Ab + (size_t)r * HDIM + k0 + c4 * 4);
            As[c4 * 4 + 0][r] = va.x; As[c4 * 4 + 1][r] = va.y;
            As[c4 * 4 + 2][r] = va.z; As[c4 * 4 + 3][r] = va.w;
            float4 vb = *(const float4*)(Bb + (size_t)r * HDIM + k0 + c4 * 4);
            Bsm[c4 * 4 + 0][r] = vb.x; Bsm[c4 * 4 + 1][r] = vb.y;
            Bsm[c4 * 4 + 2][r] = vb.z; Bsm[c4 * 4 + 3][r] = vb.w;
        }
        __syncthreads();
#pragma unroll
        for (int kk = 0; kk < 16; kk += 8) {
            float af[2][4], bfv[4][2];
#pragma unroll
            for (int mt = 0; mt < 2; mt++) {
                int rb = wm * 32 + mt * 16;
                af[mt][0] = As[kk + tq    ][rb + gq    ];
                af[mt][1] = As[kk + tq    ][rb + gq + 8];
                af[mt][2] = As[kk + tq + 4][rb + gq    ];
                af[mt][3] = As[kk + tq + 4][rb + gq + 8];
            }
#pragma unroll
            for (int nt = 0; nt < 4; nt++) {
                int cb = wn * 32 + nt * 8 + gq;
                bfv[nt][0] = Bsm[kk + tq    ][cb];
                bfv[nt][1] = Bsm[kk + tq + 4][cb];
            }
            unsigned ah[2][4], al[2][4], bh[4][2], bl[4][2];
#pragma unroll
            for (int mt = 0; mt < 2; mt++)
#pragma unroll
                for (int i = 0; i < 4; i++) {
                    ah[mt][i] = f2tf(af[mt][i]);
                    al[mt][i] = f2tf(af[mt][i] - __uint_as_float(ah[mt][i]));
                }
#pragma unroll
            for (int nt = 0; nt < 4; nt++)
#pragma unroll
                for (int i = 0; i < 2; i++) {
                    bh[nt][i] = f2tf(bfv[nt][i]);
                    bl[nt][i] = f2tf(bfv[nt][i] - __uint_as_float(bh[nt][i]));
                }
#pragma unroll
            for (int mt = 0; mt < 2; mt++)
#pragma unroll
                for (int nt = 0; nt < 4; nt++) {
                    mma8(acc[mt][nt], al[mt], bh[nt]);
                    mma8(acc[mt][nt], ah[mt], bl[nt]);
                    mma8(acc[mt][nt], ah[mt], bh[nt]);
                }
        }
    }
#pragma unroll
    for (int mt = 0; mt < 2; mt++)
#pragma unroll
        for (int nt = 0; nt < 4; nt++)
#pragma unroll
            for (int r = 0; r < 4; r++) {
                int row = wm * 32 + mt * 16 + gq + ((r & 2) ? 8 : 0);
                int col = wn * 32 + nt * 8 + tq * 2 + (r & 1);
                C[(size_t)(m0 + row) * NEXP + col] = acc[mt][nt][r];
            }
}

// ================= router softmax + top-6 + dispatch =================
__global__ void k_init() {
    if (threadIdx.x < NEXP) g_counts[threadIdx.x] = 0;
}

__global__ void k_router() {
    int warp = threadIdx.x >> 5, lane = threadIdx.x & 31;
    int t = blockIdx.x * 8 + warp;
    float v0 = g_logits[t * NEXP + lane];
    float v1 = g_logits[t * NEXP + 32 + lane];
    float m = fmaxf(v0, v1);
#pragma unroll
    for (int s = 16; s > 0; s >>= 1) m = fmaxf(m, __shfl_xor_sync(0xffffffffu, m, s));
    float e0 = expf(v0 - m), e1 = expf(v1 - m);
    float sum = e0 + e1;
#pragma unroll
    for (int s = 16; s > 0; s >>= 1) sum += __shfl_xor_sync(0xffffffffu, sum, s);
    float inv = 1.0f / sum;
    float p0 = e0 * inv, p1 = e1 * inv;

#pragma unroll
    for (int k = 0; k < TOPK; k++) {
        float bv; int bi;
        if (p0 >= p1) { bv = p0; bi = lane; } else { bv = p1; bi = lane + 32; }
#pragma unroll
        for (int s = 16; s > 0; s >>= 1) {
            float ov = __shfl_xor_sync(0xffffffffu, bv, s);
            int   oi = __shfl_xor_sync(0xffffffffu, bi, s);
            if (ov > bv || (ov == bv && oi < bi)) { bv = ov; bi = oi; }
        }
        if (lane == 0) {
            int pos = atomicAdd(&g_counts[bi], 1);
            if (pos < CAP) {
                g_buf_tok[bi * CAP + pos] = t;
                g_buf_w[bi * CAP + pos] = bv;
            }
        }
        if (bi < 32) { if (lane == bi) p0 = -1.0f; }
        else         { if (lane == bi - 32) p1 = -1.0f; }
    }
}

// ================= launch =================
extern "C" void kernel_launch(void* const* d_in, const int* in_sizes, int n_in,
                              void* d_out, int out_size) {
    const float* x   = (const float*)d_in[0];
    const float* gw  = (const float*)d_in[1];
    const float* gup = (const float*)d_in[2];
    const float* dwn = (const float*)d_in[3];
    const float* sgw = (const float*)d_in[4];
    const float* suw = (const float*)d_in[5];
    const float* sdw = (const float*)d_in[6];
    float* out = (float*)d_out;

    float *p_logits, *p_hid, *p_shid;
    cudaGetSymbolAddress((void**)&p_logits, g_logits);
    cudaGetSymbolAddress((void**)&p_hid,  g_hid);
    cudaGetSymbolAddress((void**)&p_shid, g_shid);

    cudaFuncSetAttribute(k_swiglu<1,0,0>, cudaFuncAttributeMaxDynamicSharedMemorySize, SWIGLU_SMEM);
    cudaFuncSetAttribute(k_swiglu<0,1,1>, cudaFuncAttributeMaxDynamicSharedMemorySize, SWIGLU_SMEM);

    k_init<<<1, 64>>>();
    // router: near-fp32 logits so top-k matches reference exactly
    k_router_gemm<<<dim3(1, NTOK / 64), RTH>>>(x, gw, p_logits);
    k_router<<<NTOK / 8, 256>>>();

    // shared experts: fused SwiGLU up ([N,K] weights), then down -> out (plain store covers out)
    k_swiglu<1,0,0><<<dim3(SIDIM / 128, NTOK / 128), NTH, SWIGLU_SMEM>>>(
        x, sgw, suw, p_shid, HDIM, 0, SIDIM, 0, 0);
    k_gemm<1,0,0><<<dim3(HDIM / 128, NTOK / 128), NTH>>>(
        p_shid, sdw, out, SIDIM, 0, HDIM, 0, 0);

    // routed experts: fused SwiGLU gate_up (gathered A, [K,N] weights), down (atomic scatter-add)
    k_swiglu<0,1,1><<<dim3(IDIM / 128, CAP / 128, NEXP), NTH, SWIGLU_SMEM>>>(
        x, gup, gup + IDIM, p_hid, HDIM, TWOI, IDIM, (long)HDIM * TWOI, (long)CAP * IDIM);
    k_gemm<0,1,1><<<dim3(HDIM / 128, CAP / 128, NEXP), NTH>>>(
        p_hid, dwn, out, IDIM, HDIM, HDIM, (long)CAP * IDIM, (long)IDIM * HDIM);
}

// round 10
// speedup vs baseline: 1.7137x; 1.1649x over previous
#include <cuda_runtime.h>
#include <cuda_fp16.h>
#include <math.h>
#include <stdint.h>

// ---------------- problem constants ----------------
#define NTOK   2048
#define NEXP   64
#define TOPK   6
#define CAP    512
#define HDIM   2048
#define IDIM   768
#define TWOI   1536
#define SIDIM  1536

// ---------------- tile config ----------------
#define BK   32              // k per slab (halfs)
#define NTH  256             // 8 warps
#define RSA  80              // [row][k] tile row stride BYTES (32 halfs + 16 pad)
#define RSB  272             // [k][n] tile row stride BYTES (128 halfs + 8 pad)
#define TSLOT 10240          // bytes per tile slot (A:128*80; B-kn:32*272=8704 fits)
#define SWIGLU_SMEM (9 * TSLOT)   // 3 stages x (A,G,U) = 92160 B
#define GEMM_SMEM   (6 * TSLOT)   // 3 stages x (A,B)   = 61440 B

// ---------------- scratch ----------------
__device__ int   g_counts[NEXP];
__device__ int   g_buf_tok[NEXP * CAP];
__device__ float g_buf_w[NEXP * CAP];
__device__ float g_logits[NTOK * NEXP];
__device__ float g_hid[(size_t)NEXP * CAP * IDIM];
__device__ float g_shid[(size_t)NTOK * SIDIM];

// ---------------- helpers ----------------
__device__ __forceinline__ uint32_t smem_u32(const void* p) {
    uint32_t a;
    asm("{ .reg .u64 t; cvta.to.shared.u64 t, %1; cvt.u32.u64 %0, t; }" : "=r"(a) : "l"(p));
    return a;
}
__device__ __forceinline__ uint32_t pack2(float a, float b) {
    __half2 h = __floats2half2_rn(a, b);
    return *(uint32_t*)&h;
}
__device__ __forceinline__ void ldsm4(uint32_t r[4], uint32_t addr) {
    asm volatile("ldmatrix.sync.aligned.m8n8.x4.shared.b16 {%0,%1,%2,%3}, [%4];"
                 : "=r"(r[0]), "=r"(r[1]), "=r"(r[2]), "=r"(r[3]) : "r"(addr));
}
__device__ __forceinline__ void ldsm4t(uint32_t r[4], uint32_t addr) {
    asm volatile("ldmatrix.sync.aligned.m8n8.x4.trans.shared.b16 {%0,%1,%2,%3}, [%4];"
                 : "=r"(r[0]), "=r"(r[1]), "=r"(r[2]), "=r"(r[3]) : "r"(addr));
}
__device__ __forceinline__ void mma16(float c[4], const uint32_t a[4], const uint32_t b[2]) {
    asm volatile(
        "mma.sync.aligned.m16n8k16.row.col.f32.f16.f16.f32 "
        "{%0,%1,%2,%3}, {%4,%5,%6,%7}, {%8,%9}, {%0,%1,%2,%3};"
        : "+f"(c[0]), "+f"(c[1]), "+f"(c[2]), "+f"(c[3])
        : "r"(a[0]), "r"(a[1]), "r"(a[2]), "r"(a[3]), "r"(b[0]), "r"(b[1]));
}
__device__ __forceinline__ unsigned f2tf(float x) {
    unsigned y;
    asm("cvt.rna.tf32.f32 %0, %1;" : "=r"(y) : "f"(x));
    return y;
}
__device__ __forceinline__ void mma8(float c[4], const unsigned a[4], const unsigned b[2]) {
    asm volatile(
        "mma.sync.aligned.m16n8k8.row.col.f32.tf32.tf32.f32 "
        "{%0,%1,%2,%3}, {%4,%5,%6,%7}, {%8,%9}, {%0,%1,%2,%3};"
        : "+f"(c[0]), "+f"(c[1]), "+f"(c[2]), "+f"(c[3])
        : "r"(a[0]), "r"(a[1]), "r"(a[2]), "r"(a[3]), "r"(b[0]), "r"(b[1]));
}
__device__ __forceinline__ float silu_f(float v) { return v / (1.0f + expf(-v)); }

// ldmatrix per-lane byte offsets:
#define LM_A(lane)  (((((lane) >> 3) & 1) * 8 + ((lane) & 7)) * RSA + ((lane) >> 4) * 16)
#define LM_BN(lane) ((((lane) >> 4) * 8 + ((lane) & 7)) * RSA + (((lane) >> 3) & 1) * 16)
#define LM_BT(lane) (((((lane) >> 3) & 1) * 8 + ((lane) & 7)) * RSB + ((lane) >> 4) * 16)

// ================= fused SwiGLU up-projection (fp16, BK=32, 3-stage) =================
template<int BNK, int EXPERT, int GATHER>
__global__ __launch_bounds__(NTH) void k_swiglu(
    const float* __restrict__ Abase, const float* __restrict__ Bg0,
    const float* __restrict__ Bu0, float* __restrict__ C,
    int Kd, int ldb, int ldc, long sB, long sC)
{
    extern __shared__ __align__(16) unsigned char smraw[];
    __shared__ int s_tok[128];

    const int tid = threadIdx.x;
    const int warp = tid >> 5, lane = tid & 31;
    const int wm = warp >> 2, wn = warp & 3;
    const int gq = lane >> 2, tq = lane & 3;
    const int m0 = blockIdx.y * 128, n0 = blockIdx.x * 128;

    int e = 0, cnt = 0x40000000;
    if (EXPERT) {
        e = blockIdx.z;
        cnt = g_counts[e];
        if (m0 >= cnt) return;
    }
    if (GATHER) {
        if (tid < 128) {
            int p = m0 + tid;
            s_tok[tid] = (p < cnt) ? g_buf_tok[e * CAP + p] : 0;
        }
        __syncthreads();
    }

    const uint32_t smb = smem_u32(smraw);

    // ---- loaders: 4 float4 chunks each for A / G / U per slab ----
    const float* pa[4];
    uint32_t stA[4];
#pragma unroll
    for (int j = 0; j < 4; j++) {
        int idx = tid + j * NTH;            // 0..1023
        int m = idx >> 3, k8 = idx & 7;     // row, 4-float chunk
        if (GATHER) pa[j] = Abase + (size_t)s_tok[m] * Kd + k8 * 4;
        else        pa[j] = Abase + (size_t)(m0 + m) * Kd + k8 * 4;
        stA[j] = (uint32_t)(m * RSA + k8 * 8);
    }
    const float* pg[4]; const float* pu[4];
    uint32_t stB[4];
#pragma unroll
    for (int j = 0; j < 4; j++) {
        int idx = tid + j * NTH;
        if (BNK) {
            int n = idx >> 3, k8 = idx & 7;
            pg[j] = Bg0 + (EXPERT ? (size_t)e * sB : 0) + (size_t)(n0 + n) * Kd + k8 * 4;
            pu[j] = Bu0 + (EXPERT ? (size_t)e * sB : 0) + (size_t)(n0 + n) * Kd + k8 * 4;
            stB[j] = (uint32_t)(n * RSA + k8 * 8);
        } else {
            int k = idx >> 5, n8 = idx & 31;
            pg[j] = Bg0 + (EXPERT ? (size_t)e * sB : 0) + (size_t)k * ldb + n0 + n8 * 4;
            pu[j] = Bu0 + (EXPERT ? (size_t)e * sB : 0) + (size_t)k * ldb + n0 + n8 * 4;
            stB[j] = (uint32_t)(k * RSB + n8 * 8);
        }
    }
    const long bumpB = BNK ? (long)BK : (long)BK * ldb;

    float4 ra[4], rg[4], ru[4];
    auto LDG = [&]() {
#pragma unroll
        for (int j = 0; j < 4; j++) { ra[j] = *(const float4*)pa[j]; pa[j] += BK; }
#pragma unroll
        for (int j = 0; j < 4; j++) { rg[j] = *(const float4*)pg[j]; pg[j] += bumpB; }
#pragma unroll
        for (int j = 0; j < 4; j++) { ru[j] = *(const float4*)pu[j]; pu[j] += bumpB; }
    };
    auto STS = [&](int buf) {
        uint32_t aT = smb + buf * TSLOT;
        uint32_t gT = smb + 3 * TSLOT + buf * TSLOT;
        uint32_t uT = smb + 6 * TSLOT + buf * TSLOT;
#pragma unroll
        for (int j = 0; j < 4; j++) {
            uint2 v = make_uint2(pack2(ra[j].x, ra[j].y), pack2(ra[j].z, ra[j].w));
            asm volatile("st.shared.v2.u32 [%0], {%1, %2};" :: "r"(aT + stA[j]), "r"(v.x), "r"(v.y));
        }
#pragma unroll
        for (int j = 0; j < 4; j++) {
            uint2 vg = make_uint2(pack2(rg[j].x, rg[j].y), pack2(rg[j].z, rg[j].w));
            asm volatile("st.shared.v2.u32 [%0], {%1, %2};" :: "r"(gT + stB[j]), "r"(vg.x), "r"(vg.y));
            uint2 vu = make_uint2(pack2(ru[j].x, ru[j].y), pack2(ru[j].z, ru[j].w));
            asm volatile("st.shared.v2.u32 [%0], {%1, %2};" :: "r"(uT + stB[j]), "r"(vu.x), "r"(vu.y));
        }
    };

    uint32_t aOff[4];
#pragma unroll
    for (int mt = 0; mt < 4; mt++) aOff[mt] = (uint32_t)((wm * 64 + mt * 16) * RSA) + LM_A(lane);
    uint32_t bOff[2];
#pragma unroll
    for (int p = 0; p < 2; p++)
        bOff[p] = BNK ? (uint32_t)((wn * 32 + p * 16) * RSA) + LM_BN(lane)
                      : (uint32_t)((wn * 32 + p * 16) * 2) + LM_BT(lane);

    float accg[4][4][4], accu[4][4][4];
#pragma unroll
    for (int mt = 0; mt < 4; mt++)
#pragma unroll
        for (int nt = 0; nt < 4; nt++)
#pragma unroll
            for (int r = 0; r < 4; r++) { accg[mt][nt][r] = 0.0f; accu[mt][nt][r] = 0.0f; }

    const int nslab = Kd / BK;
    LDG(); STS(0);
    LDG(); STS(1);
    __syncthreads();

    int bc = 0, bs = 2;
    for (int s = 0; s < nslab; s++) {
        const bool pf = (s + 2 < nslab);
        if (pf) LDG();
        uint32_t aT = smb + bc * TSLOT;
        uint32_t gT = smb + 3 * TSLOT + bc * TSLOT;
        uint32_t uT = smb + 6 * TSLOT + bc * TSLOT;

#pragma unroll
        for (int kh = 0; kh < 2; kh++) {
            const uint32_t kA = kh * 32;                       // +16 halfs in RSA tiles
            const uint32_t kB = BNK ? (uint32_t)(kh * 32) : (uint32_t)(kh * 16 * RSB);
            uint32_t af[4][4];
#pragma unroll
            for (int mt = 0; mt < 4; mt++) ldsm4(af[mt], aT + aOff[mt] + kA);
            uint32_t bg[4][2], bu[4][2];
#pragma unroll
            for (int p = 0; p < 2; p++) {
                uint32_t t[4];
                if (BNK) ldsm4(t, gT + bOff[p] + kB); else ldsm4t(t, gT + bOff[p] + kB);
                bg[2 * p][0] = t[0]; bg[2 * p][1] = t[1];
                bg[2 * p + 1][0] = t[2]; bg[2 * p + 1][1] = t[3];
                if (BNK) ldsm4(t, uT + bOff[p] + kB); else ldsm4t(t, uT + bOff[p] + kB);
                bu[2 * p][0] = t[0]; bu[2 * p][1] = t[1];
                bu[2 * p + 1][0] = t[2]; bu[2 * p + 1][1] = t[3];
            }
#pragma unroll
            for (int mt = 0; mt < 4; mt++)
#pragma unroll
                for (int nt = 0; nt < 4; nt++) {
                    mma16(accg[mt][nt], af[mt], bg[nt]);
                    mma16(accu[mt][nt], af[mt], bu[nt]);
                }
        }
        __syncthreads();
        if (pf) STS(bs);
        bc = (bc == 2) ? 0 : bc + 1;
        bs = (bs == 2) ? 0 : bs + 1;
    }

    // ---- epilogue: silu(g)*u ----
#pragma unroll
    for (int mt = 0; mt < 4; mt++)
#pragma unroll
        for (int nt = 0; nt < 4; nt++)
#pragma unroll
            for (int r = 0; r < 4; r++) {
                int row = wm * 64 + mt * 16 + gq + ((r & 2) ? 8 : 0);
                int col = wn * 32 + nt * 8 + tq * 2 + (r & 1);
                int gm = m0 + row;
                if (EXPERT && gm >= cnt) continue;
                float g = accg[mt][nt][r], u = accu[mt][nt][r];
                float* dst = C + (EXPERT ? (size_t)e * sC : 0);
                dst[(size_t)gm * ldc + n0 + col] = silu_f(g) * u;
            }
}

// ================= down GEMM (fp16, BK=32, 3-stage; 128x128 block) =================
template<int BNK, int EXPERT, int ATOMIC>
__global__ __launch_bounds__(NTH) void k_gemm(
    const float* __restrict__ Abase, const float* __restrict__ Bbase,
    float* __restrict__ C, int Kd, int ldb, int ldc,
    long sA, long sB)
{
    extern __shared__ __align__(16) unsigned char smraw[];
    __shared__ int   s_tok[128];
    __shared__ float s_w[128];

    const int tid = threadIdx.x;
    const int warp = tid >> 5, lane = tid & 31;
    const int wm = warp >> 2, wn = warp & 3;
    const int gq = lane >> 2, tq = lane & 3;
    const int m0 = blockIdx.y * 128, n0 = blockIdx.x * 128;

    int e = 0, cnt = 0x40000000;
    if (EXPERT) {
        e = blockIdx.z;
        cnt = g_counts[e];
        if (m0 >= cnt) return;
    }
    if (ATOMIC) {
        if (tid < 128) {
            int p = m0 + tid;
            int ok = (p < cnt);
            s_tok[tid] = ok ? g_buf_tok[e * CAP + p] : 0;
            s_w[tid]   = ok ? g_buf_w[e * CAP + p] : 0.0f;
        }
        __syncthreads();
    }

    const uint32_t smb = smem_u32(smraw);

    const float* pa[4];
    uint32_t stA[4];
#pragma unroll
    for (int j = 0; j < 4; j++) {
        int idx = tid + j * NTH;
        int m = idx >> 3, k8 = idx & 7;
        pa[j] = Abase + (EXPERT ? (size_t)e * sA : 0) + (size_t)(m0 + m) * Kd + k8 * 4;
        stA[j] = (uint32_t)(m * RSA + k8 * 8);
    }
    const float* pb[4];
    uint32_t stB[4];
#pragma unroll
    for (int j = 0; j < 4; j++) {
        int idx = tid + j * NTH;
        if (BNK) {
            int n = idx >> 3, k8 = idx & 7;
            pb[j] = Bbase + (EXPERT ? (size_t)e * sB : 0) + (size_t)(n0 + n) * Kd + k8 * 4;
            stB[j] = (uint32_t)(n * RSA + k8 * 8);
        } else {
            int k = idx >> 5, n8 = idx & 31;
            pb[j] = Bbase + (EXPERT ? (size_t)e * sB : 0) + (size_t)k * ldb + n0 + n8 * 4;
            stB[j] = (uint32_t)(k * RSB + n8 * 8);
        }
    }
    const long bumpB = BNK ? (long)BK : (long)BK * ldb;

    float4 ra[4], rb[4];
    auto LDG = [&]() {
#pragma unroll
        for (int j = 0; j < 4; j++) { ra[j] = *(const float4*)pa[j]; pa[j] += BK; }
#pragma unroll
        for (int j = 0; j < 4; j++) { rb[j] = *(const float4*)pb[j]; pb[j] += bumpB; }
    };
    auto STS = [&](int buf) {
        uint32_t aT = smb + buf * TSLOT;
        uint32_t bT = smb + 3 * TSLOT + buf * TSLOT;
#pragma unroll
        for (int j = 0; j < 4; j++) {
            uint2 v = make_uint2(pack2(ra[j].x, ra[j].y), pack2(ra[j].z, ra[j].w));
            asm volatile("st.shared.v2.u32 [%0], {%1, %2};" :: "r"(aT + stA[j]), "r"(v.x), "r"(v.y));
        }
#pragma unroll
        for (int j = 0; j < 4; j++) {
            uint2 v = make_uint2(pack2(rb[j].x, rb[j].y), pack2(rb[j].z, rb[j].w));
            asm volatile("st.shared.v2.u32 [%0], {%1, %2};" :: "r"(bT + stB[j]), "r"(v.x), "r"(v.y));
        }
    };

    uint32_t aOff[4];
#pragma unroll
    for (int mt = 0; mt < 4; mt++) aOff[mt] = (uint32_t)((wm * 64 + mt * 16) * RSA) + LM_A(lane);
    uint32_t bOff[2];
#pragma unroll
    for (int p = 0; p < 2; p++)
        bOff[p] = BNK ? (uint32_t)((wn * 32 + p * 16) * RSA) + LM_BN(lane)
                      : (uint32_t)((wn * 32 + p * 16) * 2) + LM_BT(lane);

    float acc[4][4][4];
#pragma unroll
    for (int mt = 0; mt < 4; mt++)
#pragma unroll
        for (int nt = 0; nt < 4; nt++)
#pragma unroll
            for (int r = 0; r < 4; r++) acc[mt][nt][r] = 0.0f;

    const int nslab = Kd / BK;
    LDG(); STS(0);
    LDG(); STS(1);
    __syncthreads();

    int bc = 0, bs = 2;
    for (int s = 0; s < nslab; s++) {
        const bool pf = (s + 2 < nslab);
        if (pf) LDG();
        uint32_t aT = smb + bc * TSLOT;
        uint32_t bT = smb + 3 * TSLOT + bc * TSLOT;

#pragma unroll
        for (int kh = 0; kh < 2; kh++) {
            const uint32_t kA = kh * 32;
            const uint32_t kB = BNK ? (uint32_t)(kh * 32) : (uint32_t)(kh * 16 * RSB);
            uint32_t af[4][4];
#pragma unroll
            for (int mt = 0; mt < 4; mt++) ldsm4(af[mt], aT + aOff[mt] + kA);
            uint32_t bf[4][2];
#pragma unroll
            for (int p = 0; p < 2; p++) {
                uint32_t t[4];
                if (BNK) ldsm4(t, bT + bOff[p] + kB); else ldsm4t(t, bT + bOff[p] + kB);
                bf[2 * p][0] = t[0]; bf[2 * p][1] = t[1];
                bf[2 * p + 1][0] = t[2]; bf[2 * p + 1][1] = t[3];
            }
#pragma unroll
            for (int mt = 0; mt < 4; mt++)
#pragma unroll
                for (int nt = 0; nt < 4; nt++)
                    mma16(acc[mt][nt], af[mt], bf[nt]);
        }
        __syncthreads();
        if (pf) STS(bs);
        bc = (bc == 2) ? 0 : bc + 1;
        bs = (bs == 2) ? 0 : bs + 1;
    }

#pragma unroll
    for (int mt = 0; mt < 4; mt++)
#pragma unroll
        for (int nt = 0; nt < 4; nt++)
#pragma unroll
            for (int r = 0; r < 4; r++) {
                int row = wm * 64 + mt * 16 + gq + ((r & 2) ? 8 : 0);
                int col = wn * 32 + nt * 8 + tq * 2 + (r & 1);
                int gm = m0 + row;
                if (EXPERT && gm >= cnt) continue;
                if (ATOMIC) {
                    atomicAdd(&C[(size_t)s_tok[row] * ldc + n0 + col],
                              acc[mt][nt][r] * s_w[row]);
                } else {
                    C[(size_t)gm * ldc + n0 + col] = acc[mt][nt][r];
                }
            }
}

// ================= router logits: 3xTF32 (near-fp32, exact top-k) =================
#define RTH 128
__global__ __launch_bounds__(RTH) void k_router_gemm(const float* __restrict__ A,
                                                     const float* __restrict__ B,
                                                     float* __restrict__ C) {
    __shared__ float As[16][64 + 4];
    __shared__ float Bsm[16][64 + 4];
    int tid = threadIdx.x;
    int warp = tid >> 5, lane = tid & 31;
    int wm = warp >> 1, wn = warp & 1, gq = lane >> 2, tq = lane & 3;
    int m0 = blockIdx.y * 64;

    const float* Ab = A + (size_t)m0 * HDIM;
    const float* Bb = B;

    float acc[2][4][4];
#pragma unroll
    for (int mt = 0; mt < 2; mt++)
#pragma unroll
        for (int nt = 0; nt < 4; nt++)
#pragma unroll
            for (int r = 0; r < 4; r++) acc[mt][nt][r] = 0.0f;

    for (int k0 = 0; k0 < HDIM; k0 += 16) {
        __syncthreads();
#pragma unroll
        for (int j = 0; j < 2; j++) {
            int it = tid + j * RTH;
            int r = it >> 2, c4 = it & 3;
            float4 va = *(const float4*)(Ab + (size_t)r * HDIM + k0 + c4 * 4);
            As[c4 * 4 + 0][r] = va.x; As[c4 * 4 + 1][r] = va.y;
            As[c4 * 4 + 2][r] = va.z; As[c4 * 4 + 3][r] = va.w;
            float4 vb = *(const float4*)(Bb + (size_t)r * HDIM + k0 + c4 * 4);
            Bsm[c4 * 4 + 0][r] = vb.x; Bsm[c4 * 4 + 1][r] = vb.y;
            Bsm[c4 * 4 + 2][r] = vb.z; Bsm[c4 * 4 + 3][r] = vb.w;
        }
        __syncthreads();
#pragma unroll
        for (int kk = 0; kk < 16; kk += 8) {
            float af[2][4], bfv[4][2];
#pragma unroll
            for (int mt = 0; mt < 2; mt++) {
                int rb = wm * 32 + mt * 16;
                af[mt][0] = As[kk + tq    ][rb + gq    ];
                af[mt][1] = As[kk + tq    ][rb + gq + 8];
                af[mt][2] = As[kk + tq + 4][rb + gq    ];
                af[mt][3] = As[kk + tq + 4][rb + gq + 8];
            }
#pragma unroll
            for (int nt = 0; nt < 4; nt++) {
                int cb = wn * 32 + nt * 8 + gq;
                bfv[nt][0] = Bsm[kk + tq    ][cb];
                bfv[nt][1] = Bsm[kk + tq + 4][cb];
            }
            unsigned ah[2][4], al[2][4], bh[4][2], bl[4][2];
#pragma unroll
            for (int mt = 0; mt < 2; mt++)
#pragma unroll
                for (int i = 0; i < 4; i++) {
                    ah[mt][i] = f2tf(af[mt][i]);
                    al[mt][i] = f2tf(af[mt][i] - __uint_as_float(ah[mt][i]));
                }
#pragma unroll
            for (int nt = 0; nt < 4; nt++)
#pragma unroll
                for (int i = 0; i < 2; i++) {
                    bh[nt][i] = f2tf(bfv[nt][i]);
                    bl[nt][i] = f2tf(bfv[nt][i] - __uint_as_float(bh[nt][i]));
                }
#pragma unroll
            for (int mt = 0; mt < 2; mt++)
#pragma unroll
                for (int nt = 0; nt < 4; nt++) {
                    mma8(acc[mt][nt], al[mt], bh[nt]);
                    mma8(acc[mt][nt], ah[mt], bl[nt]);
                    mma8(acc[mt][nt], ah[mt], bh[nt]);
                }
        }
    }
#pragma unroll
    for (int mt = 0; mt < 2; mt++)
#pragma unroll
        for (int nt = 0; nt < 4; nt++)
#pragma unroll
            for (int r = 0; r < 4; r++) {
                int row = wm * 32 + mt * 16 + gq + ((r & 2) ? 8 : 0);
                int col = wn * 32 + nt * 8 + tq * 2 + (r & 1);
                C[(size_t)(m0 + row) * NEXP + col] = acc[mt][nt][r];
            }
}

// ================= router softmax + top-6 + dispatch =================
__global__ void k_init() {
    if (threadIdx.x < NEXP) g_counts[threadIdx.x] = 0;
}

__global__ void k_router() {
    int warp = threadIdx.x >> 5, lane = threadIdx.x & 31;
    int t = blockIdx.x * 8 + warp;
    float v0 = g_logits[t * NEXP + lane];
    float v1 = g_logits[t * NEXP + 32 + lane];
    float m = fmaxf(v0, v1);
#pragma unroll
    for (int s = 16; s > 0; s >>= 1) m = fmaxf(m, __shfl_xor_sync(0xffffffffu, m, s));
    float e0 = expf(v0 - m), e1 = expf(v1 - m);
    float sum = e0 + e1;
#pragma unroll
    for (int s = 16; s > 0; s >>= 1) sum += __shfl_xor_sync(0xffffffffu, sum, s);
    float inv = 1.0f / sum;
    float p0 = e0 * inv, p1 = e1 * inv;

#pragma unroll
    for (int k = 0; k < TOPK; k++) {
        float bv; int bi;
        if (p0 >= p1) { bv = p0; bi = lane; } else { bv = p1; bi = lane + 32; }
#pragma unroll
        for (int s = 16; s > 0; s >>= 1) {
            float ov = __shfl_xor_sync(0xffffffffu, bv, s);
            int   oi = __shfl_xor_sync(0xffffffffu, bi, s);
            if (ov > bv || (ov == bv && oi < bi)) { bv = ov; bi = oi; }
        }
        if (lane == 0) {
            int pos = atomicAdd(&g_counts[bi], 1);
            if (pos < CAP) {
                g_buf_tok[bi * CAP + pos] = t;
                g_buf_w[bi * CAP + pos] = bv;
            }
        }
        if (bi < 32) { if (lane == bi) p0 = -1.0f; }
        else         { if (lane == bi - 32) p1 = -1.0f; }
    }
}

// ================= launch =================
extern "C" void kernel_launch(void* const* d_in, const int* in_sizes, int n_in,
                              void* d_out, int out_size) {
    const float* x   = (const float*)d_in[0];
    const float* gw  = (const float*)d_in[1];
    const float* gup = (const float*)d_in[2];
    const float* dwn = (const float*)d_in[3];
    const float* sgw = (const float*)d_in[4];
    const float* suw = (const float*)d_in[5];
    const float* sdw = (const float*)d_in[6];
    float* out = (float*)d_out;

    float *p_logits, *p_hid, *p_shid;
    cudaGetSymbolAddress((void**)&p_logits, g_logits);
    cudaGetSymbolAddress((void**)&p_hid,  g_hid);
    cudaGetSymbolAddress((void**)&p_shid, g_shid);

    cudaFuncSetAttribute(k_swiglu<1,0,0>, cudaFuncAttributeMaxDynamicSharedMemorySize, SWIGLU_SMEM);
    cudaFuncSetAttribute(k_swiglu<0,1,1>, cudaFuncAttributeMaxDynamicSharedMemorySize, SWIGLU_SMEM);
    cudaFuncSetAttribute(k_gemm<1,0,0>,   cudaFuncAttributeMaxDynamicSharedMemorySize, GEMM_SMEM);
    cudaFuncSetAttribute(k_gemm<0,1,1>,   cudaFuncAttributeMaxDynamicSharedMemorySize, GEMM_SMEM);

    k_init<<<1, 64>>>();
    // router: near-fp32 logits so top-k matches reference exactly
    k_router_gemm<<<dim3(1, NTOK / 64), RTH>>>(x, gw, p_logits);
    k_router<<<NTOK / 8, 256>>>();

    // shared experts: fused SwiGLU up ([N,K] weights), then down -> out (plain store covers out)
    k_swiglu<1,0,0><<<dim3(SIDIM / 128, NTOK / 128), NTH, SWIGLU_SMEM>>>(
        x, sgw, suw, p_shid, HDIM, 0, SIDIM, 0, 0);
    k_gemm<1,0,0><<<dim3(HDIM / 128, NTOK / 128), NTH, GEMM_SMEM>>>(
        p_shid, sdw, out, SIDIM, 0, HDIM, 0, 0);

    // routed experts: fused SwiGLU gate_up (gathered A, [K,N] weights), down (atomic scatter-add)
    k_swiglu<0,1,1><<<dim3(IDIM / 128, CAP / 128, NEXP), NTH, SWIGLU_SMEM>>>(
        x, gup, gup + IDIM, p_hid, HDIM, TWOI, IDIM, (long)HDIM * TWOI, (long)CAP * IDIM);
    k_gemm<0,1,1><<<dim3(HDIM / 128, CAP / 128, NEXP), NTH, GEMM_SMEM>>>(
        p_hid, dwn, out, IDIM, HDIM, HDIM, (long)CAP * IDIM, (long)IDIM * HDIM);
}

// round 11
// speedup vs baseline: 1.9226x; 1.1219x over previous
#include <cuda_runtime.h>
#include <cuda_fp16.h>
#include <math.h>
#include <stdint.h>

// ---------------- problem constants ----------------
#define NTOK   2048
#define NEXP   64
#define TOPK   6
#define CAP    512
#define HDIM   2048
#define IDIM   768
#define TWOI   1536
#define SIDIM  1536

// ---------------- tile config ----------------
#define BK   32              // k per slab (halfs)
#define NTH  256             // 8 warps
#define RSA  80              // [row][k] tile row stride BYTES (32 halfs + 16 pad)
#define RSB  272             // [k][n] tile row stride BYTES (128 halfs + 8 pad)
#define TSLOT 10240          // bytes per tile slot
#define SWIGLU_SMEM (12 * TSLOT)  // 4-slot ring x (A,G,U) = 122880 B
#define GEMM_SMEM   (8 * TSLOT)   // 4-slot ring x (A,B)   = 81920 B

// router K-split
#define RKC 4
#define RKLEN (HDIM / RKC)   // 512

// ---------------- scratch ----------------
__device__ int   g_counts[NEXP];
__device__ int   g_buf_tok[NEXP * CAP];
__device__ float g_buf_w[NEXP * CAP];
__device__ float g_logits_p[RKC * NTOK * NEXP];
__device__ float g_hid[(size_t)NEXP * CAP * IDIM];
__device__ float g_shid[(size_t)NTOK * SIDIM];

// ---------------- helpers ----------------
__device__ __forceinline__ uint32_t smem_u32(const void* p) {
    uint32_t a;
    asm("{ .reg .u64 t; cvta.to.shared.u64 t, %1; cvt.u32.u64 %0, t; }" : "=r"(a) : "l"(p));
    return a;
}
__device__ __forceinline__ uint32_t pack2(float a, float b) {
    __half2 h = __floats2half2_rn(a, b);
    return *(uint32_t*)&h;
}
__device__ __forceinline__ void ldsm4(uint32_t r[4], uint32_t addr) {
    asm volatile("ldmatrix.sync.aligned.m8n8.x4.shared.b16 {%0,%1,%2,%3}, [%4];"
                 : "=r"(r[0]), "=r"(r[1]), "=r"(r[2]), "=r"(r[3]) : "r"(addr));
}
__device__ __forceinline__ void ldsm4t(uint32_t r[4], uint32_t addr) {
    asm volatile("ldmatrix.sync.aligned.m8n8.x4.trans.shared.b16 {%0,%1,%2,%3}, [%4];"
                 : "=r"(r[0]), "=r"(r[1]), "=r"(r[2]), "=r"(r[3]) : "r"(addr));
}
__device__ __forceinline__ void mma16(float c[4], const uint32_t a[4], const uint32_t b[2]) {
    asm volatile(
        "mma.sync.aligned.m16n8k16.row.col.f32.f16.f16.f32 "
        "{%0,%1,%2,%3}, {%4,%5,%6,%7}, {%8,%9}, {%0,%1,%2,%3};"
        : "+f"(c[0]), "+f"(c[1]), "+f"(c[2]), "+f"(c[3])
        : "r"(a[0]), "r"(a[1]), "r"(a[2]), "r"(a[3]), "r"(b[0]), "r"(b[1]));
}
__device__ __forceinline__ unsigned f2tf(float x) {
    unsigned y;
    asm("cvt.rna.tf32.f32 %0, %1;" : "=r"(y) : "f"(x));
    return y;
}
__device__ __forceinline__ void mma8(float c[4], const unsigned a[4], const unsigned b[2]) {
    asm volatile(
        "mma.sync.aligned.m16n8k8.row.col.f32.tf32.tf32.f32 "
        "{%0,%1,%2,%3}, {%4,%5,%6,%7}, {%8,%9}, {%0,%1,%2,%3};"
        : "+f"(c[0]), "+f"(c[1]), "+f"(c[2]), "+f"(c[3])
        : "r"(a[0]), "r"(a[1]), "r"(a[2]), "r"(a[3]), "r"(b[0]), "r"(b[1]));
}
__device__ __forceinline__ float silu_f(float v) { return v / (1.0f + expf(-v)); }

// ldmatrix per-lane byte offsets:
#define LM_A(lane)  (((((lane) >> 3) & 1) * 8 + ((lane) & 7)) * RSA + ((lane) >> 4) * 16)
#define LM_BN(lane) ((((lane) >> 4) * 8 + ((lane) & 7)) * RSA + (((lane) >> 3) & 1) * 16)
#define LM_BT(lane) (((((lane) >> 3) & 1) * 8 + ((lane) & 7)) * RSB + ((lane) >> 4) * 16)

// ================= fused SwiGLU up-projection (fp16, BK=32, 4-slot ring) =================
template<int BNK, int EXPERT, int GATHER>
__global__ __launch_bounds__(NTH) void k_swiglu(
    const float* __restrict__ Abase, const float* __restrict__ Bg0,
    const float* __restrict__ Bu0, float* __restrict__ C,
    int Kd, int ldb, int ldc, long sB, long sC)
{
    extern __shared__ __align__(16) unsigned char smraw[];
    __shared__ int s_tok[128];

    const int tid = threadIdx.x;
    const int warp = tid >> 5, lane = tid & 31;
    const int wm = warp >> 2, wn = warp & 3;
    const int gq = lane >> 2, tq = lane & 3;
    const int m0 = blockIdx.y * 128, n0 = blockIdx.x * 128;

    int e = 0, cnt = 0x40000000;
    if (EXPERT) {
        e = blockIdx.z;
        cnt = g_counts[e];
        if (m0 >= cnt) return;
    }
    if (GATHER) {
        if (tid < 128) {
            int p = m0 + tid;
            s_tok[tid] = (p < cnt) ? g_buf_tok[e * CAP + p] : 0;
        }
        __syncthreads();
    }

    const uint32_t smb = smem_u32(smraw);

    // ---- loaders ----
    const float* pa[4];
    uint32_t stA[4];
#pragma unroll
    for (int j = 0; j < 4; j++) {
        int idx = tid + j * NTH;
        int m = idx >> 3, k8 = idx & 7;
        if (GATHER) pa[j] = Abase + (size_t)s_tok[m] * Kd + k8 * 4;
        else        pa[j] = Abase + (size_t)(m0 + m) * Kd + k8 * 4;
        stA[j] = (uint32_t)(m * RSA + k8 * 8);
    }
    const float* pg[4]; const float* pu[4];
    uint32_t stB[4];
#pragma unroll
    for (int j = 0; j < 4; j++) {
        int idx = tid + j * NTH;
        if (BNK) {
            int n = idx >> 3, k8 = idx & 7;
            pg[j] = Bg0 + (EXPERT ? (size_t)e * sB : 0) + (size_t)(n0 + n) * Kd + k8 * 4;
            pu[j] = Bu0 + (EXPERT ? (size_t)e * sB : 0) + (size_t)(n0 + n) * Kd + k8 * 4;
            stB[j] = (uint32_t)(n * RSA + k8 * 8);
        } else {
            int k = idx >> 5, n8 = idx & 31;
            pg[j] = Bg0 + (EXPERT ? (size_t)e * sB : 0) + (size_t)k * ldb + n0 + n8 * 4;
            pu[j] = Bu0 + (EXPERT ? (size_t)e * sB : 0) + (size_t)k * ldb + n0 + n8 * 4;
            stB[j] = (uint32_t)(k * RSB + n8 * 8);
        }
    }
    const long bumpB = BNK ? (long)BK : (long)BK * ldb;

    float4 ra[4], rg[4], ru[4];
    auto LDG = [&]() {
#pragma unroll
        for (int j = 0; j < 4; j++) { ra[j] = *(const float4*)pa[j]; pa[j] += BK; }
#pragma unroll
        for (int j = 0; j < 4; j++) { rg[j] = *(const float4*)pg[j]; pg[j] += bumpB; }
#pragma unroll
        for (int j = 0; j < 4; j++) { ru[j] = *(const float4*)pu[j]; pu[j] += bumpB; }
    };
    auto STS = [&](int slot) {
        uint32_t aT = smb + slot * TSLOT;
        uint32_t gT = smb + 4 * TSLOT + slot * TSLOT;
        uint32_t uT = smb + 8 * TSLOT + slot * TSLOT;
#pragma unroll
        for (int j = 0; j < 4; j++) {
            uint2 v = make_uint2(pack2(ra[j].x, ra[j].y), pack2(ra[j].z, ra[j].w));
            asm volatile("st.shared.v2.u32 [%0], {%1, %2};" :: "r"(aT + stA[j]), "r"(v.x), "r"(v.y));
        }
#pragma unroll
        for (int j = 0; j < 4; j++) {
            uint2 vg = make_uint2(pack2(rg[j].x, rg[j].y), pack2(rg[j].z, rg[j].w));
            asm volatile("st.shared.v2.u32 [%0], {%1, %2};" :: "r"(gT + stB[j]), "r"(vg.x), "r"(vg.y));
            uint2 vu = make_uint2(pack2(ru[j].x, ru[j].y), pack2(ru[j].z, ru[j].w));
            asm volatile("st.shared.v2.u32 [%0], {%1, %2};" :: "r"(uT + stB[j]), "r"(vu.x), "r"(vu.y));
        }
    };

    uint32_t aOff[4];
#pragma unroll
    for (int mt = 0; mt < 4; mt++) aOff[mt] = (uint32_t)((wm * 64 + mt * 16) * RSA) + LM_A(lane);
    uint32_t bOff[2];
#pragma unroll
    for (int p = 0; p < 2; p++)
        bOff[p] = BNK ? (uint32_t)((wn * 32 + p * 16) * RSA) + LM_BN(lane)
                      : (uint32_t)((wn * 32 + p * 16) * 2) + LM_BT(lane);

    float accg[4][4][4], accu[4][4][4];
#pragma unroll
    for (int mt = 0; mt < 4; mt++)
#pragma unroll
        for (int nt = 0; nt < 4; nt++)
#pragma unroll
            for (int r = 0; r < 4; r++) { accg[mt][nt][r] = 0.0f; accu[mt][nt][r] = 0.0f; }

    auto COMPUTE = [&](int slot) {
        uint32_t aT = smb + slot * TSLOT;
        uint32_t gT = smb + 4 * TSLOT + slot * TSLOT;
        uint32_t uT = smb + 8 * TSLOT + slot * TSLOT;
#pragma unroll
        for (int kh = 0; kh < 2; kh++) {
            const uint32_t kA = kh * 32;
            const uint32_t kB = BNK ? (uint32_t)(kh * 32) : (uint32_t)(kh * 16 * RSB);
            uint32_t af[4][4];
#pragma unroll
            for (int mt = 0; mt < 4; mt++) ldsm4(af[mt], aT + aOff[mt] + kA);
            uint32_t bg[4][2], bu[4][2];
#pragma unroll
            for (int p = 0; p < 2; p++) {
                uint32_t t[4];
                if (BNK) ldsm4(t, gT + bOff[p] + kB); else ldsm4t(t, gT + bOff[p] + kB);
                bg[2 * p][0] = t[0]; bg[2 * p][1] = t[1];
                bg[2 * p + 1][0] = t[2]; bg[2 * p + 1][1] = t[3];
                if (BNK) ldsm4(t, uT + bOff[p] + kB); else ldsm4t(t, uT + bOff[p] + kB);
                bu[2 * p][0] = t[0]; bu[2 * p][1] = t[1];
                bu[2 * p + 1][0] = t[2]; bu[2 * p + 1][1] = t[3];
            }
#pragma unroll
            for (int mt = 0; mt < 4; mt++)
#pragma unroll
                for (int nt = 0; nt < 4; nt++) {
                    mma16(accg[mt][nt], af[mt], bg[nt]);
                    mma16(accu[mt][nt], af[mt], bu[nt]);
                }
        }
    };

    const int nslab = Kd / BK;
    // ---- prologue: fill slots 0,1 ----
    LDG(); STS(0);
    LDG(); STS(1);

    // ---- mainloop: one sync per TWO slabs ----
    for (int t = 0; t < nslab / 2; t++) {
        __syncthreads();
        const int s0 = 2 * t, s1 = 2 * t + 1;
        const bool pf0 = (s0 + 2 < nslab), pf1 = (s1 + 2 < nslab);
        if (pf0) LDG();
        COMPUTE(s0 & 3);
        if (pf0) STS((s0 + 2) & 3);
        if (pf1) LDG();
        COMPUTE(s1 & 3);
        if (pf1) STS((s1 + 2) & 3);
    }

    // ---- epilogue: silu(g)*u ----
#pragma unroll
    for (int mt = 0; mt < 4; mt++)
#pragma unroll
        for (int nt = 0; nt < 4; nt++)
#pragma unroll
            for (int r = 0; r < 4; r++) {
                int row = wm * 64 + mt * 16 + gq + ((r & 2) ? 8 : 0);
                int col = wn * 32 + nt * 8 + tq * 2 + (r & 1);
                int gm = m0 + row;
                if (EXPERT && gm >= cnt) continue;
                float g = accg[mt][nt][r], u = accu[mt][nt][r];
                float* dst = C + (EXPERT ? (size_t)e * sC : 0);
                dst[(size_t)gm * ldc + n0 + col] = silu_f(g) * u;
            }
}

// ================= down GEMM (fp16, BK=32, 4-slot ring; 128x128 block) =================
template<int BNK, int EXPERT, int ATOMIC>
__global__ __launch_bounds__(NTH) void k_gemm(
    const float* __restrict__ Abase, const float* __restrict__ Bbase,
    float* __restrict__ C, int Kd, int ldb, int ldc,
    long sA, long sB)
{
    extern __shared__ __align__(16) unsigned char smraw[];
    __shared__ int   s_tok[128];
    __shared__ float s_w[128];

    const int tid = threadIdx.x;
    const int warp = tid >> 5, lane = tid & 31;
    const int wm = warp >> 2, wn = warp & 3;
    const int gq = lane >> 2, tq = lane & 3;
    const int m0 = blockIdx.y * 128, n0 = blockIdx.x * 128;

    int e = 0, cnt = 0x40000000;
    if (EXPERT) {
        e = blockIdx.z;
        cnt = g_counts[e];
        if (m0 >= cnt) return;
    }
    if (ATOMIC) {
        if (tid < 128) {
            int p = m0 + tid;
            int ok = (p < cnt);
            s_tok[tid] = ok ? g_buf_tok[e * CAP + p] : 0;
            s_w[tid]   = ok ? g_buf_w[e * CAP + p] : 0.0f;
        }
        __syncthreads();
    }

    const uint32_t smb = smem_u32(smraw);

    const float* pa[4];
    uint32_t stA[4];
#pragma unroll
    for (int j = 0; j < 4; j++) {
        int idx = tid + j * NTH;
        int m = idx >> 3, k8 = idx & 7;
        pa[j] = Abase + (EXPERT ? (size_t)e * sA : 0) + (size_t)(m0 + m) * Kd + k8 * 4;
        stA[j] = (uint32_t)(m * RSA + k8 * 8);
    }
    const float* pb[4];
    uint32_t stB[4];
#pragma unroll
    for (int j = 0; j < 4; j++) {
        int idx = tid + j * NTH;
        if (BNK) {
            int n = idx >> 3, k8 = idx & 7;
            pb[j] = Bbase + (EXPERT ? (size_t)e * sB : 0) + (size_t)(n0 + n) * Kd + k8 * 4;
            stB[j] = (uint32_t)(n * RSA + k8 * 8);
        } else {
            int k = idx >> 5, n8 = idx & 31;
            pb[j] = Bbase + (EXPERT ? (size_t)e * sB : 0) + (size_t)k * ldb + n0 + n8 * 4;
            stB[j] = (uint32_t)(k * RSB + n8 * 8);
        }
    }
    const long bumpB = BNK ? (long)BK : (long)BK * ldb;

    float4 ra[4], rb[4];
    auto LDG = [&]() {
#pragma unroll
        for (int j = 0; j < 4; j++) { ra[j] = *(const float4*)pa[j]; pa[j] += BK; }
#pragma unroll
        for (int j = 0; j < 4; j++) { rb[j] = *(const float4*)pb[j]; pb[j] += bumpB; }
    };
    auto STS = [&](int slot) {
        uint32_t aT = smb + slot * TSLOT;
        uint32_t bT = smb + 4 * TSLOT + slot * TSLOT;
#pragma unroll
        for (int j = 0; j < 4; j++) {
            uint2 v = make_uint2(pack2(ra[j].x, ra[j].y), pack2(ra[j].z, ra[j].w));
            asm volatile("st.shared.v2.u32 [%0], {%1, %2};" :: "r"(aT + stA[j]), "r"(v.x), "r"(v.y));
        }
#pragma unroll
        for (int j = 0; j < 4; j++) {
            uint2 v = make_uint2(pack2(rb[j].x, rb[j].y), pack2(rb[j].z, rb[j].w));
            asm volatile("st.shared.v2.u32 [%0], {%1, %2};" :: "r"(bT + stB[j]), "r"(v.x), "r"(v.y));
        }
    };

    uint32_t aOff[4];
#pragma unroll
    for (int mt = 0; mt < 4; mt++) aOff[mt] = (uint32_t)((wm * 64 + mt * 16) * RSA) + LM_A(lane);
    uint32_t bOff[2];
#pragma unroll
    for (int p = 0; p < 2; p++)
        bOff[p] = BNK ? (uint32_t)((wn * 32 + p * 16) * RSA) + LM_BN(lane)
                      : (uint32_t)((wn * 32 + p * 16) * 2) + LM_BT(lane);

    float acc[4][4][4];
#pragma unroll
    for (int mt = 0; mt < 4; mt++)
#pragma unroll
        for (int nt = 0; nt < 4; nt++)
#pragma unroll
            for (int r = 0; r < 4; r++) acc[mt][nt][r] = 0.0f;

    auto COMPUTE = [&](int slot) {
        uint32_t aT = smb + slot * TSLOT;
        uint32_t bT = smb + 4 * TSLOT + slot * TSLOT;
#pragma unroll
        for (int kh = 0; kh < 2; kh++) {
            const uint32_t kA = kh * 32;
            const uint32_t kB = BNK ? (uint32_t)(kh * 32) : (uint32_t)(kh * 16 * RSB);
            uint32_t af[4][4];
#pragma unroll
            for (int mt = 0; mt < 4; mt++) ldsm4(af[mt], aT + aOff[mt] + kA);
            uint32_t bf[4][2];
#pragma unroll
            for (int p = 0; p < 2; p++) {
                uint32_t t[4];
                if (BNK) ldsm4(t, bT + bOff[p] + kB); else ldsm4t(t, bT + bOff[p] + kB);
                bf[2 * p][0] = t[0]; bf[2 * p][1] = t[1];
                bf[2 * p + 1][0] = t[2]; bf[2 * p + 1][1] = t[3];
            }
#pragma unroll
            for (int mt = 0; mt < 4; mt++)
#pragma unroll
                for (int nt = 0; nt < 4; nt++)
                    mma16(acc[mt][nt], af[mt], bf[nt]);
        }
    };

    const int nslab = Kd / BK;
    LDG(); STS(0);
    LDG(); STS(1);

    for (int t = 0; t < nslab / 2; t++) {
        __syncthreads();
        const int s0 = 2 * t, s1 = 2 * t + 1;
        const bool pf0 = (s0 + 2 < nslab), pf1 = (s1 + 2 < nslab);
        if (pf0) LDG();
        COMPUTE(s0 & 3);
        if (pf0) STS((s0 + 2) & 3);
        if (pf1) LDG();
        COMPUTE(s1 & 3);
        if (pf1) STS((s1 + 2) & 3);
    }

#pragma unroll
    for (int mt = 0; mt < 4; mt++)
#pragma unroll
        for (int nt = 0; nt < 4; nt++)
#pragma unroll
            for (int r = 0; r < 4; r++) {
                int row = wm * 64 + mt * 16 + gq + ((r & 2) ? 8 : 0);
                int col = wn * 32 + nt * 8 + tq * 2 + (r & 1);
                int gm = m0 + row;
                if (EXPERT && gm >= cnt) continue;
                if (ATOMIC) {
                    atomicAdd(&C[(size_t)s_tok[row] * ldc + n0 + col],
                              acc[mt][nt][r] * s_w[row]);
                } else {
                    C[(size_t)gm * ldc + n0 + col] = acc[mt][nt][r];
                }
            }
}

// ================= router logits: 3xTF32, K-split x4 (near-fp32, exact top-k) =================
#define RTH 128
__global__ __launch_bounds__(RTH) void k_router_gemm(const float* __restrict__ A,
                                                     const float* __restrict__ B) {
    __shared__ float As[16][64 + 4];
    __shared__ float Bsm[16][64 + 4];
    int tid = threadIdx.x;
    int warp = tid >> 5, lane = tid & 31;
    int wm = warp >> 1, wn = warp & 1, gq = lane >> 2, tq = lane & 3;
    int m0 = blockIdx.y * 64;
    int kc = blockIdx.x;                       // K chunk 0..3
    int kbase = kc * RKLEN;

    const float* Ab = A + (size_t)m0 * HDIM + kbase;
    const float* Bb = B + kbase;

    float acc[2][4][4];
#pragma unroll
    for (int mt = 0; mt < 2; mt++)
#pragma unroll
        for (int nt = 0; nt < 4; nt++)
#pragma unroll
            for (int r = 0; r < 4; r++) acc[mt][nt][r] = 0.0f;

    for (int k0 = 0; k0 < RKLEN; k0 += 16) {
        __syncthreads();
#pragma unroll
        for (int j = 0; j < 2; j++) {
            int it = tid + j * RTH;
            int r = it >> 2, c4 = it & 3;
            float4 va = *(const float4*)(Ab + (size_t)r * HDIM + k0 + c4 * 4);
            As[c4 * 4 + 0][r] = va.x; As[c4 * 4 + 1][r] = va.y;
            As[c4 * 4 + 2][r] = va.z; As[c4 * 4 + 3][r] = va.w;
            float4 vb = *(const float4*)(Bb + (size_t)r * HDIM + k0 + c4 * 4);
            Bsm[c4 * 4 + 0][r] = vb.x; Bsm[c4 * 4 + 1][r] = vb.y;
            Bsm[c4 * 4 + 2][r] = vb.z; Bsm[c4 * 4 + 3][r] = vb.w;
        }
        __syncthreads();
#pragma unroll
        for (int kk = 0; kk < 16; kk += 8) {
            float af[2][4], bfv[4][2];
#pragma unroll
            for (int mt = 0; mt < 2; mt++) {
                int rb = wm * 32 + mt * 16;
                af[mt][0] = As[kk + tq    ][rb + gq    ];
                af[mt][1] = As[kk + tq    ][rb + gq + 8];
                af[mt][2] = As[kk + tq + 4][rb + gq    ];
                af[mt][3] = As[kk + tq + 4][rb + gq + 8];
            }
#pragma unroll
            for (int nt = 0; nt < 4; nt++) {
                int cb = wn * 32 + nt * 8 + gq;
                bfv[nt][0] = Bsm[kk + tq    ][cb];
                bfv[nt][1] = Bsm[kk + tq + 4][cb];
            }
            unsigned ah[2][4], al[2][4], bh[4][2], bl[4][2];
#pragma unroll
            for (int mt = 0; mt < 2; mt++)
#pragma unroll
                for (int i = 0; i < 4; i++) {
                    ah[mt][i] = f2tf(af[mt][i]);
                    al[mt][i] = f2tf(af[mt][i] - __uint_as_float(ah[mt][i]));
                }
#pragma unroll
            for (int nt = 0; nt < 4; nt++)
#pragma unroll
                for (int i = 0; i < 2; i++) {
                    bh[nt][i] = f2tf(bfv[nt][i]);
                    bl[nt][i] = f2tf(bfv[nt][i] - __uint_as_float(bh[nt][i]));
                }
#pragma unroll
            for (int mt = 0; mt < 2; mt++)
#pragma unroll
                for (int nt = 0; nt < 4; nt++) {
                    mma8(acc[mt][nt], al[mt], bh[nt]);
                    mma8(acc[mt][nt], ah[mt], bl[nt]);
                    mma8(acc[mt][nt], ah[mt], bh[nt]);
                }
        }
    }
    float* dst = g_logits_p + (size_t)kc * NTOK * NEXP;
#pragma unroll
    for (int mt = 0; mt < 2; mt++)
#pragma unroll
        for (int nt = 0; nt < 4; nt++)
#pragma unroll
            for (int r = 0; r < 4; r++) {
                int row = wm * 32 + mt * 16 + gq + ((r & 2) ? 8 : 0);
                int col = wn * 32 + nt * 8 + tq * 2 + (r & 1);
                dst[(size_t)(m0 + row) * NEXP + col] = acc[mt][nt][r];
            }
}

// ================= router softmax + top-6 + dispatch =================
__global__ void k_init() {
    if (threadIdx.x < NEXP) g_counts[threadIdx.x] = 0;
}

__global__ void k_router() {
    int warp = threadIdx.x >> 5, lane = threadIdx.x & 31;
    int t = blockIdx.x * 8 + warp;
    // deterministic fixed-order reduction of the 4 K-chunk partials
    float v0 = 0.0f, v1 = 0.0f;
#pragma unroll
    for (int c = 0; c < RKC; c++) {
        v0 += g_logits_p[(size_t)c * NTOK * NEXP + t * NEXP + lane];
        v1 += g_logits_p[(size_t)c * NTOK * NEXP + t * NEXP + 32 + lane];
    }
    float m = fmaxf(v0, v1);
#pragma unroll
    for (int s = 16; s > 0; s >>= 1) m = fmaxf(m, __shfl_xor_sync(0xffffffffu, m, s));
    float e0 = expf(v0 - m), e1 = expf(v1 - m);
    float sum = e0 + e1;
#pragma unroll
    for (int s = 16; s > 0; s >>= 1) sum += __shfl_xor_sync(0xffffffffu, sum, s);
    float inv = 1.0f / sum;
    float p0 = e0 * inv, p1 = e1 * inv;

#pragma unroll
    for (int k = 0; k < TOPK; k++) {
        float bv; int bi;
        if (p0 >= p1) { bv = p0; bi = lane; } else { bv = p1; bi = lane + 32; }
#pragma unroll
        for (int s = 16; s > 0; s >>= 1) {
            float ov = __shfl_xor_sync(0xffffffffu, bv, s);
            int   oi = __shfl_xor_sync(0xffffffffu, bi, s);
            if (ov > bv || (ov == bv && oi < bi)) { bv = ov; bi = oi; }
        }
        if (lane == 0) {
            int pos = atomicAdd(&g_counts[bi], 1);
            if (pos < CAP) {
                g_buf_tok[bi * CAP + pos] = t;
                g_buf_w[bi * CAP + pos] = bv;
            }
        }
        if (bi < 32) { if (lane == bi) p0 = -1.0f; }
        else         { if (lane == bi - 32) p1 = -1.0f; }
    }
}

// ================= launch =================
extern "C" void kernel_launch(void* const* d_in, const int* in_sizes, int n_in,
                              void* d_out, int out_size) {
    const float* x   = (const float*)d_in[0];
    const float* gw  = (const float*)d_in[1];
    const float* gup = (const float*)d_in[2];
    const float* dwn = (const float*)d_in[3];
    const float* sgw = (const float*)d_in[4];
    const float* suw = (const float*)d_in[5];
    const float* sdw = (const float*)d_in[6];
    float* out = (float*)d_out;

    float *p_hid, *p_shid;
    cudaGetSymbolAddress((void**)&p_hid,  g_hid);
    cudaGetSymbolAddress((void**)&p_shid, g_shid);

    cudaFuncSetAttribute(k_swiglu<1,0,0>, cudaFuncAttributeMaxDynamicSharedMemorySize, SWIGLU_SMEM);
    cudaFuncSetAttribute(k_swiglu<0,1,1>, cudaFuncAttributeMaxDynamicSharedMemorySize, SWIGLU_SMEM);
    cudaFuncSetAttribute(k_gemm<1,0,0>,   cudaFuncAttributeMaxDynamicSharedMemorySize, GEMM_SMEM);
    cudaFuncSetAttribute(k_gemm<0,1,1>,   cudaFuncAttributeMaxDynamicSharedMemorySize, GEMM_SMEM);

    k_init<<<1, 64>>>();
    // router: near-fp32 logits (K-split x4, deterministic reduce in k_router)
    k_router_gemm<<<dim3(RKC, NTOK / 64), RTH>>>(x, gw);
    k_router<<<NTOK / 8, 256>>>();

    // shared experts: fused SwiGLU up ([N,K] weights), then down -> out (plain store covers out)
    k_swiglu<1,0,0><<<dim3(SIDIM / 128, NTOK / 128), NTH, SWIGLU_SMEM>>>(
        x, sgw, suw, p_shid, HDIM, 0, SIDIM, 0, 0);
    k_gemm<1,0,0><<<dim3(HDIM / 128, NTOK / 128), NTH, GEMM_SMEM>>>(
        p_shid, sdw, out, SIDIM, 0, HDIM, 0, 0);

    // routed experts: fused SwiGLU gate_up (gathered A, [K,N] weights), down (atomic scatter-add)
    k_swiglu<0,1,1><<<dim3(IDIM / 128, CAP / 128, NEXP), NTH, SWIGLU_SMEM>>>(
        x, gup, gup + IDIM, p_hid, HDIM, TWOI, IDIM, (long)HDIM * TWOI, (long)CAP * IDIM);
    k_gemm<0,1,1><<<dim3(HDIM / 128, CAP / 128, NEXP), NTH, GEMM_SMEM>>>(
        p_hid, dwn, out, IDIM, HDIM, HDIM, (long)CAP * IDIM, (long)IDIM * HDIM);
}